// round 3
// baseline (speedup 1.0000x reference)
#include <cuda_runtime.h>
#include <math.h>

// Problem constants
#define TB   8192   // T
#define NB   128    // batch
#define NS   512    // states
#define NM   64     // symbols
#define NCL  16     // clusters (batch groups)
#define RPC  8      // batch rows per cluster
#define CPC  8      // CTAs per cluster (state slices)
#define NC   64     // state columns per CTA

// Static device scratch (no allocations allowed)
__device__ unsigned short g_sym[NB * TB];            // 2 MB: symbol per (b,t)
__device__ float g_p[2][NCL][RPC][NS];               // 256 KB: double-buffered p exchange
__device__ float g_lmax[2][NCL][CPC][RPC];           // per-CTA per-row local maxes

// ---------------------------------------------------------------------------
// Kernel 0: collapse one-hot x[b,t,:] -> symbol index. 4 threads per position.
// ---------------------------------------------------------------------------
__global__ void extract_sym_kernel(const float* __restrict__ x) {
    int g = blockIdx.x * blockDim.x + threadIdx.x;   // grid sized exactly
    int pos  = g >> 2;
    int part = g & 3;
    const float4* xp = reinterpret_cast<const float4*>(x) + (size_t)pos * 16 + part * 4;
    int found = 0;
#pragma unroll
    for (int i = 0; i < 4; i++) {
        float4 v = xp[i];
        int base = part * 16 + i * 4;
        if (v.x > 0.5f) found = base;
        if (v.y > 0.5f) found = base + 1;
        if (v.z > 0.5f) found = base + 2;
        if (v.w > 0.5f) found = base + 3;
    }
    found = max(found, __shfl_xor_sync(0xFFFFFFFFu, found, 1));
    found = max(found, __shfl_xor_sync(0xFFFFFFFFu, found, 2));
    if (part == 0) g_sym[pos] = (unsigned short)found;
}

// ---------------------------------------------------------------------------
// Kernel 1: persistent clustered forward recurrence.
//   grid = 128 CTAs, cluster (8,1,1), 256 threads.
//   CTA rank r owns states [64r, 64r+64); cluster cl owns batch rows [8cl, 8cl+8).
//   Thread (c = tid&63, q = tid>>6) holds A[q*128 .. q*128+128, 64r + c] in regs.
// ---------------------------------------------------------------------------
__global__ void __cluster_dims__(CPC, 1, 1) __launch_bounds__(256, 1)
hmm_fwd_kernel(const float* __restrict__ A, const float* __restrict__ Bm,
               float* __restrict__ out)
{
    const int tid  = threadIdx.x;
    const int lane = tid & 31;
    const int warp = tid >> 5;
    const int c    = tid & 63;
    const int q    = tid >> 6;

    unsigned int r_;
    asm("mov.u32 %0, %%cluster_ctarank;" : "=r"(r_));
    const int r    = (int)r_;
    const int cl   = (int)blockIdx.x / CPC;
    const int col0 = r * NC;

    __shared__ float  p_sh[RPC][NS];        // 16 KB  full p vector (8 rows)
    __shared__ float  part_sh[4][RPC][NC];  // 8 KB   K-quarter partials
    __shared__ float  u_sh[RPC][NC];        // 2 KB   this CTA's u slice
    __shared__ float  B_sh[NM][NC];         // 16 KB  emission slice B[m, col0+c]
    __shared__ double c_sh[RPC];            // running log-scale per row
    __shared__ float  hm_sh[RPC][2];        // half-row maxes
    __shared__ unsigned short sym_sh[RPC];

    // ---- A slice into registers (constant across all 8191 steps) ----
    float Areg[128];
#pragma unroll
    for (int j = 0; j < 128; j++)
        Areg[j] = A[(size_t)(q * 128 + j) * NS + col0 + c];

    // ---- emission slice ----
    for (int i = tid; i < NM * NC; i += 256)
        B_sh[i >> 6][i & 63] = Bm[(size_t)(i >> 6) * NS + col0 + (i & 63)];

    if (tid < RPC) c_sh[tid] = 0.0;

    // ---- init: u_0 = [E(b,0,0), 0, 0, ...] into buffer 0 ----
    for (int i = tid; i < RPC * NC; i += 256) {
        int row = i >> 6, cc = i & 63;
        float v = 0.f;
        if (r == 0 && cc == 0) {
            int s0 = g_sym[(size_t)(cl * RPC + row) * TB];
            v = Bm[(size_t)s0 * NS];        // B[sym0][state 0]
        }
        g_p[0][cl][row][col0 + cc] = v;
    }
    if (tid < RPC) {
        float lm = 0.f;
        if (r == 0) {
            int s0 = g_sym[(size_t)(cl * RPC + tid) * TB];
            lm = Bm[(size_t)s0 * NS];
        }
        g_lmax[0][cl][r][tid] = lm;
    }
    __syncthreads();
    asm volatile("barrier.cluster.arrive.aligned;" ::: "memory");
    asm volatile("barrier.cluster.wait.aligned;"   ::: "memory");

    int buf = 0;
    for (int t = 1; t < TB; t++) {
        // -- symbols for this step (used in epilogue, after syncthreads) --
        if (tid < RPC)
            sym_sh[tid] = g_sym[(size_t)(cl * RPC + tid) * TB + t];

        // -- load p (warp w handles row w): global max, scale, stage to SMEM --
        {
            const int row = warp;
            float lm = (lane < CPC) ? __ldcg(&g_lmax[buf][cl][lane][row]) : 0.f;
            lm = fmaxf(lm, __shfl_xor_sync(0xFFFFFFFFu, lm, 1));
            lm = fmaxf(lm, __shfl_xor_sync(0xFFFFFFFFu, lm, 2));
            lm = fmaxf(lm, __shfl_xor_sync(0xFFFFFFFFu, lm, 4));
            float m = __shfl_sync(0xFFFFFFFFu, lm, 0);   // > 0 always
            float rinv = 1.0f / m;
            if (lane == 0) c_sh[row] += (double)logf(m);
            const float4* src = reinterpret_cast<const float4*>(&g_p[buf][cl][row][0]);
            float4*       dst = reinterpret_cast<float4*>(&p_sh[row][0]);
#pragma unroll
            for (int i = 0; i < 4; i++) {
                float4 v = __ldcg(src + lane + i * 32);
                v.x *= rinv; v.y *= rinv; v.z *= rinv; v.w *= rinv;
                dst[lane + i * 32] = v;
            }
        }
        __syncthreads();

        // -- matmul: part[q][row][c] = sum_{k in quarter q} p[row][k]*A[k][col] --
#pragma unroll 1
        for (int row = 0; row < RPC; row++) {
            const float4* pp = reinterpret_cast<const float4*>(&p_sh[row][q * 128]);
            float a0 = 0.f, a1 = 0.f, a2 = 0.f, a3 = 0.f;
#pragma unroll
            for (int j4 = 0; j4 < 32; j4++) {
                float4 pv = pp[j4];                       // LDS.128 broadcast
                a0 = fmaf(Areg[j4 * 4 + 0], pv.x, a0);
                a1 = fmaf(Areg[j4 * 4 + 1], pv.y, a1);
                a2 = fmaf(Areg[j4 * 4 + 2], pv.z, a2);
                a3 = fmaf(Areg[j4 * 4 + 3], pv.w, a3);
            }
            part_sh[q][row][c] = (a0 + a1) + (a2 + a3);
        }
        __syncthreads();

        // -- epilogue: reduce quarters, apply E, local max, publish --
        const int bufn = buf ^ 1;
#pragma unroll
        for (int h = 0; h < 2; h++) {
            const int row = (tid >> 6) + h * 4;
            float u = (part_sh[0][row][c] + part_sh[1][row][c])
                    + (part_sh[2][row][c] + part_sh[3][row][c]);
            u *= B_sh[sym_sh[row]][c];                   // E_t multiply
            u_sh[row][c] = u;
            g_p[bufn][cl][row][col0 + c] = u;
            float wm = u;
            wm = fmaxf(wm, __shfl_xor_sync(0xFFFFFFFFu, wm, 16));
            wm = fmaxf(wm, __shfl_xor_sync(0xFFFFFFFFu, wm, 8));
            wm = fmaxf(wm, __shfl_xor_sync(0xFFFFFFFFu, wm, 4));
            wm = fmaxf(wm, __shfl_xor_sync(0xFFFFFFFFu, wm, 2));
            wm = fmaxf(wm, __shfl_xor_sync(0xFFFFFFFFu, wm, 1));
            if (lane == 0) hm_sh[row][(tid >> 5) & 1] = wm;
        }
        __syncthreads();
        if (tid < RPC)
            g_lmax[bufn][cl][r][tid] = fmaxf(hm_sh[tid][0], hm_sh[tid][1]);

        asm volatile("barrier.cluster.arrive.aligned;" ::: "memory");
        asm volatile("barrier.cluster.wait.aligned;"   ::: "memory");
        buf = bufn;
    }

    // ---- alpha_T = log(u_T) + C ----
#pragma unroll
    for (int h = 0; h < 2; h++) {
        const int row = (tid >> 6) + h * 4;
        float u = u_sh[row][c];
        out[(size_t)(cl * RPC + row) * NS + col0 + c] =
            (float)((double)logf(u) + c_sh[row]);
    }
}

// ---------------------------------------------------------------------------
// Kernel 2: loglik[b] = log(sum_s exp(alpha - m) + S*eps) + m, one warp per row
// ---------------------------------------------------------------------------
__global__ void loglik_kernel(float* __restrict__ out) {
    const int b    = blockIdx.x;
    const int lane = threadIdx.x;
    const float* a = out + (size_t)b * NS;
    float v[16];
    float m = -3.0e38f;
#pragma unroll
    for (int i = 0; i < 16; i++) { v[i] = a[lane + i * 32]; m = fmaxf(m, v[i]); }
#pragma unroll
    for (int o = 16; o >= 1; o >>= 1) m = fmaxf(m, __shfl_xor_sync(0xFFFFFFFFu, m, o));
    float s = 0.f;
#pragma unroll
    for (int i = 0; i < 16; i++) s += expf(v[i] - m);
#pragma unroll
    for (int o = 16; o >= 1; o >>= 1) s += __shfl_xor_sync(0xFFFFFFFFu, s, o);
    if (lane == 0) out[NB * NS + b] = logf(s + 512.0f * 1e-16f) + m;
}

// ---------------------------------------------------------------------------
extern "C" void kernel_launch(void* const* d_in, const int* in_sizes, int n_in,
                              void* d_out, int out_size) {
    const float* x  = nullptr;
    const float* A  = nullptr;
    const float* Bm = nullptr;
    for (int i = 0; i < n_in; i++) {
        if      (in_sizes[i] == NB * TB * NM) x  = (const float*)d_in[i];
        else if (in_sizes[i] == NS * NS)      A  = (const float*)d_in[i];
        else if (in_sizes[i] == NM * NS)      Bm = (const float*)d_in[i];
    }
    // fallback to declared order (x, A, B)
    if (!x  && n_in > 0) x  = (const float*)d_in[0];
    if (!A  && n_in > 1) A  = (const float*)d_in[1];
    if (!Bm && n_in > 2) Bm = (const float*)d_in[2];

    float* out = (float*)d_out;

    extract_sym_kernel<<<(NB * TB * 4) / 256, 256>>>(x);
    hmm_fwd_kernel<<<NCL * CPC, 256>>>(A, Bm, out);
    if (out_size >= NB * NS + NB)
        loglik_kernel<<<NB, 32>>>(out);
}

// round 5
// speedup vs baseline: 1.3902x; 1.3902x over previous
#include <cuda_runtime.h>
#include <math.h>

// Problem constants
#define TB   8192   // T
#define NB   128    // batch
#define NS   512    // states
#define NM   64     // symbols
#define NCL  16     // clusters (batch groups)
#define RPC  8      // batch rows per cluster
#define CPC  8      // CTAs per cluster (state slices)
#define NC   64     // state columns per CTA

// Dynamic SMEM layout (bytes)
#define SM_P     0            // p_sh   [RPC][NS]        16384
#define SM_PART  16384        // part_sh[8][RPC][NC]     16384
#define SM_B     32768        // B_sh   [NM][NC]         16384
#define SM_C     49152        // c_sh   [RPC] double        64
#define SM_SYM   49216        // sym_sh [RPC] u16            16
#define SM_TOTAL 49280

// Static device scratch (no allocations allowed)
__device__ unsigned short g_sym[NB * TB];            // 2 MB: symbol per (b,t)
__device__ float g_p[2][NCL][RPC][NS];               // double-buffered p exchange

// ---- packed fp32x2 helpers -------------------------------------------------
__device__ __forceinline__ void ffma2(unsigned long long& acc,
                                      unsigned long long a,
                                      unsigned long long b) {
    asm("fma.rn.f32x2 %0, %1, %2, %0;" : "+l"(acc) : "l"(a), "l"(b));
}
__device__ __forceinline__ unsigned long long pack2(float x, float y) {
    unsigned long long r;
    asm("mov.b64 %0, {%1, %2};" : "=l"(r) : "f"(x), "f"(y));
    return r;
}
__device__ __forceinline__ float2 unpack2(unsigned long long v) {
    float2 r;
    asm("mov.b64 {%0, %1}, %2;" : "=f"(r.x), "=f"(r.y) : "l"(v));
    return r;
}

// ---------------------------------------------------------------------------
// Kernel 0: collapse one-hot x[b,t,:] -> symbol index. 4 threads per position.
// ---------------------------------------------------------------------------
__global__ void extract_sym_kernel(const float* __restrict__ x) {
    int g = blockIdx.x * blockDim.x + threadIdx.x;
    int pos  = g >> 2;
    int part = g & 3;
    const float4* xp = reinterpret_cast<const float4*>(x) + (size_t)pos * 16 + part * 4;
    int found = 0;
#pragma unroll
    for (int i = 0; i < 4; i++) {
        float4 v = xp[i];
        int base = part * 16 + i * 4;
        if (v.x > 0.5f) found = base;
        if (v.y > 0.5f) found = base + 1;
        if (v.z > 0.5f) found = base + 2;
        if (v.w > 0.5f) found = base + 3;
    }
    found = max(found, __shfl_xor_sync(0xFFFFFFFFu, found, 1));
    found = max(found, __shfl_xor_sync(0xFFFFFFFFu, found, 2));
    if (part == 0) g_sym[pos] = (unsigned short)found;
}

// ---------------------------------------------------------------------------
// Kernel 1: persistent clustered forward recurrence.
//   grid = 128 CTAs, cluster (8,1,1), 256 threads, dynamic SMEM 49280 B.
//   CTA rank r owns states [64r, 64r+64); cluster cl owns batch rows [8cl..].
//   Thread (cp = tid&31, g = tid>>5): columns {cp, cp+32} of the slice,
//   K-octant [64g, 64g+64). A pairs live in 128 registers as f32x2.
// ---------------------------------------------------------------------------
__global__ void __cluster_dims__(CPC, 1, 1) __launch_bounds__(256, 1)
hmm_fwd_kernel(const float* __restrict__ A, const float* __restrict__ Bm,
               float* __restrict__ out)
{
    extern __shared__ char smem_raw[];
    float (*p_sh)[NS]            = reinterpret_cast<float(*)[NS]>(smem_raw + SM_P);
    float (*part_sh)[RPC][NC]    = reinterpret_cast<float(*)[RPC][NC]>(smem_raw + SM_PART);
    float (*B_sh)[NC]            = reinterpret_cast<float(*)[NC]>(smem_raw + SM_B);
    double* c_sh                 = reinterpret_cast<double*>(smem_raw + SM_C);
    unsigned short* sym_sh       = reinterpret_cast<unsigned short*>(smem_raw + SM_SYM);

    const int tid  = threadIdx.x;
    const int lane = tid & 31;
    const int warp = tid >> 5;
    const int c    = tid & 63;   // epilogue column
    const int cp   = tid & 31;   // matmul column pair base
    const int g    = tid >> 5;   // K-octant == warp id

    unsigned int r_;
    asm("mov.u32 %0, %%cluster_ctarank;" : "=r"(r_));
    const int r    = (int)r_;
    const int cl   = (int)blockIdx.x / CPC;
    const int col0 = r * NC;

    // ---- A slice into registers as packed f32x2 pairs (constant all steps)
    unsigned long long a0[32], a1[32];
#pragma unroll
    for (int j = 0; j < 32; j++) {
        int k = g * 64 + 2 * j;
        float x00 = A[(size_t)k * NS + col0 + cp];
        float x01 = A[(size_t)(k + 1) * NS + col0 + cp];
        float x10 = A[(size_t)k * NS + col0 + cp + 32];
        float x11 = A[(size_t)(k + 1) * NS + col0 + cp + 32];
        a0[j] = pack2(x00, x01);
        a1[j] = pack2(x10, x11);
    }

    // ---- emission slice ----
    for (int i = tid; i < NM * NC; i += 256)
        B_sh[i >> 6][i & 63] = Bm[(size_t)(i >> 6) * NS + col0 + (i & 63)];

    if (tid < RPC) c_sh[tid] = 0.0;

    // ---- init: u_0 = [E(b,0,0), 0, ...] into buffer 0 ----
    for (int i = tid; i < RPC * NC; i += 256) {
        int row = i >> 6, cc = i & 63;
        float v = 0.f;
        if (r == 0 && cc == 0) {
            int s0 = g_sym[(size_t)(cl * RPC + row) * TB];
            v = Bm[(size_t)s0 * NS];         // B[sym0][state 0]
        }
        g_p[0][cl][row][col0 + cc] = v;
    }
    __syncthreads();
    asm volatile("barrier.cluster.arrive.aligned;" ::: "memory");
    asm volatile("barrier.cluster.wait.aligned;"   ::: "memory");

    int buf = 0;
    for (int t = 1; t < TB; t++) {
        if (tid < RPC)
            sym_sh[tid] = g_sym[(size_t)(cl * RPC + tid) * TB + t];

        // -- stage: warp w loads row w, computes its own global max, scales --
        {
            const int row = warp;
            const float4* src = reinterpret_cast<const float4*>(&g_p[buf][cl][row][0]);
            float4 v0 = __ldcg(src + lane);
            float4 v1 = __ldcg(src + lane + 32);
            float4 v2 = __ldcg(src + lane + 64);
            float4 v3 = __ldcg(src + lane + 96);
            float m = fmaxf(fmaxf(fmaxf(v0.x, v0.y), fmaxf(v0.z, v0.w)),
                            fmaxf(fmaxf(v1.x, v1.y), fmaxf(v1.z, v1.w)));
            m = fmaxf(m, fmaxf(fmaxf(fmaxf(v2.x, v2.y), fmaxf(v2.z, v2.w)),
                               fmaxf(fmaxf(v3.x, v3.y), fmaxf(v3.z, v3.w))));
#pragma unroll
            for (int o = 16; o >= 1; o >>= 1)
                m = fmaxf(m, __shfl_xor_sync(0xFFFFFFFFu, m, o));
            if (lane == 0) c_sh[row] += (double)logf(m);
            float rinv = 1.0f / m;       // consistent across CTAs (same inputs)
            float4* dst = reinterpret_cast<float4*>(&p_sh[row][0]);
            v0.x *= rinv; v0.y *= rinv; v0.z *= rinv; v0.w *= rinv;
            v1.x *= rinv; v1.y *= rinv; v1.z *= rinv; v1.w *= rinv;
            v2.x *= rinv; v2.y *= rinv; v2.z *= rinv; v2.w *= rinv;
            v3.x *= rinv; v3.y *= rinv; v3.z *= rinv; v3.w *= rinv;
            dst[lane]      = v0;
            dst[lane + 32] = v1;
            dst[lane + 64] = v2;
            dst[lane + 96] = v3;
        }
        __syncthreads();

        // -- matmul: part[g][row][{cp,cp+32}] over K-octant g (FFMA2) --
#pragma unroll 1
        for (int row = 0; row < RPC; row++) {
            const float4* pp = reinterpret_cast<const float4*>(&p_sh[row][g * 64]);
            unsigned long long acc0 = 0ull, acc1 = 0ull;
#pragma unroll
            for (int j4 = 0; j4 < 16; j4++) {
                float4 pv = pp[j4];                     // LDS.128 broadcast
                unsigned long long p01 = pack2(pv.x, pv.y);
                unsigned long long p23 = pack2(pv.z, pv.w);
                ffma2(acc0, a0[2 * j4],     p01);
                ffma2(acc1, a1[2 * j4],     p01);
                ffma2(acc0, a0[2 * j4 + 1], p23);
                ffma2(acc1, a1[2 * j4 + 1], p23);
            }
            float2 s0 = unpack2(acc0);
            float2 s1 = unpack2(acc1);
            part_sh[g][row][cp]      = s0.x + s0.y;
            part_sh[g][row][cp + 32] = s1.x + s1.y;
        }
        __syncthreads();

        // -- epilogue: reduce octants, apply E, publish --
        const int bufn = buf ^ 1;
#pragma unroll
        for (int h = 0; h < 2; h++) {
            const int row = (tid >> 6) + h * 4;
            float u = ((part_sh[0][row][c] + part_sh[1][row][c])
                     + (part_sh[2][row][c] + part_sh[3][row][c]))
                    + ((part_sh[4][row][c] + part_sh[5][row][c])
                     + (part_sh[6][row][c] + part_sh[7][row][c]));
            u *= B_sh[sym_sh[row]][c];                  // E_t multiply
            g_p[bufn][cl][row][col0 + c] = u;
        }
        asm volatile("barrier.cluster.arrive.aligned;" ::: "memory");
        asm volatile("barrier.cluster.wait.aligned;"   ::: "memory");
        buf = bufn;
    }

    // ---- alpha_T = log(u_T) + C ----
#pragma unroll
    for (int h = 0; h < 2; h++) {
        const int row = (tid >> 6) + h * 4;
        float u = __ldcg(&g_p[buf][cl][row][col0 + c]);
        out[(size_t)(cl * RPC + row) * NS + col0 + c] =
            (float)((double)logf(u) + c_sh[row]);
    }
}

// ---------------------------------------------------------------------------
// Kernel 2: loglik[b] = log(sum_s exp(alpha - m) + S*eps) + m, one warp per row
// ---------------------------------------------------------------------------
__global__ void loglik_kernel(float* __restrict__ out) {
    const int b    = blockIdx.x;
    const int lane = threadIdx.x;
    const float* a = out + (size_t)b * NS;
    float v[16];
    float m = -3.0e38f;
#pragma unroll
    for (int i = 0; i < 16; i++) { v[i] = a[lane + i * 32]; m = fmaxf(m, v[i]); }
#pragma unroll
    for (int o = 16; o >= 1; o >>= 1) m = fmaxf(m, __shfl_xor_sync(0xFFFFFFFFu, m, o));
    float s = 0.f;
#pragma unroll
    for (int i = 0; i < 16; i++) s += expf(v[i] - m);
#pragma unroll
    for (int o = 16; o >= 1; o >>= 1) s += __shfl_xor_sync(0xFFFFFFFFu, s, o);
    if (lane == 0) out[NB * NS + b] = logf(s + 512.0f * 1e-16f) + m;
}

// ---------------------------------------------------------------------------
extern "C" void kernel_launch(void* const* d_in, const int* in_sizes, int n_in,
                              void* d_out, int out_size) {
    const float* x  = nullptr;
    const float* A  = nullptr;
    const float* Bm = nullptr;
    for (int i = 0; i < n_in; i++) {
        if      (in_sizes[i] == NB * TB * NM) x  = (const float*)d_in[i];
        else if (in_sizes[i] == NS * NS)      A  = (const float*)d_in[i];
        else if (in_sizes[i] == NM * NS)      Bm = (const float*)d_in[i];
    }
    if (!x  && n_in > 0) x  = (const float*)d_in[0];
    if (!A  && n_in > 1) A  = (const float*)d_in[1];
    if (!Bm && n_in > 2) Bm = (const float*)d_in[2];

    float* out = (float*)d_out;

    // Opt into >48KB dynamic SMEM (attribute set, not an allocation; capture-safe)
    cudaFuncSetAttribute(hmm_fwd_kernel,
                         cudaFuncAttributeMaxDynamicSharedMemorySize, SM_TOTAL);

    extract_sym_kernel<<<(NB * TB * 4) / 256, 256>>>(x);
    hmm_fwd_kernel<<<NCL * CPC, 256, SM_TOTAL>>>(A, Bm, out);
    if (out_size >= NB * NS + NB)
        loglik_kernel<<<NB, 32>>>(out);
}

// round 7
// speedup vs baseline: 1.4096x; 1.0139x over previous
#include <cuda_runtime.h>
#include <math.h>

// Problem constants
#define TB   8192   // T
#define NB   128    // batch
#define NS   512    // states
#define NM   64     // symbols
#define NCL  16     // clusters (batch groups)
#define RPC  8      // batch rows per cluster
#define CPC  8      // CTAs per cluster (state slices)
#define NC   64     // state columns per CTA

// Dynamic SMEM layout (bytes)
#define SM_P     0            // p_sh   [2][RPC][NS]       32768
#define SM_PART  32768        // part_sh[8][RPC][NC]       16384
#define SM_B     49152        // B_sh   [NM][NC]           16384
#define SM_LMAX  65536        // lmax   [2][RPC][CPC][2]    1024
#define SM_C     66560        // c_sh   [RPC] double          64
#define SM_RINV  66624        // rinv   [RPC] float           32
#define SM_SYM   66656        // sym    [RPC] u16             16
#define SM_TOTAL 66688

// Static device scratch
__device__ unsigned short g_sym[NB * TB];            // 2 MB: symbol per (b,t)

// ---- packed fp32x2 / DSMEM helpers ----------------------------------------
__device__ __forceinline__ void ffma2(unsigned long long& acc,
                                      unsigned long long a,
                                      unsigned long long b) {
    asm("fma.rn.f32x2 %0, %1, %2, %0;" : "+l"(acc) : "l"(a), "l"(b));
}
__device__ __forceinline__ unsigned long long pack2(float x, float y) {
    unsigned long long r;
    asm("mov.b64 %0, {%1, %2};" : "=l"(r) : "f"(x), "f"(y));
    return r;
}
__device__ __forceinline__ float2 unpack2(unsigned long long v) {
    float2 r;
    asm("mov.b64 {%0, %1}, %2;" : "=f"(r.x), "=f"(r.y) : "l"(v));
    return r;
}
__device__ __forceinline__ unsigned int mapa_sh(unsigned int addr, unsigned int rank) {
    unsigned int d;
    asm("mapa.shared::cluster.u32 %0, %1, %2;" : "=r"(d) : "r"(addr), "r"(rank));
    return d;
}
__device__ __forceinline__ void st_cluster_f32(unsigned int addr, float v) {
    asm volatile("st.shared::cluster.f32 [%0], %1;" :: "r"(addr), "f"(v) : "memory");
}
__device__ __forceinline__ float warp_max_f32(float v) {
#pragma unroll
    for (int o = 16; o >= 1; o >>= 1)
        v = fmaxf(v, __shfl_xor_sync(0xFFFFFFFFu, v, o));
    return v;
}
__device__ __forceinline__ unsigned int smem_u32(const void* p) {
    unsigned int a;
    asm("{ .reg .u64 t; cvta.to.shared.u64 t, %1; cvt.u32.u64 %0, t; }"
        : "=r"(a) : "l"(p));
    return a;
}

// ---------------------------------------------------------------------------
// Kernel 0: collapse one-hot x[b,t,:] -> symbol index. 4 threads per position.
// ---------------------------------------------------------------------------
__global__ void extract_sym_kernel(const float* __restrict__ x) {
    int g = blockIdx.x * blockDim.x + threadIdx.x;
    int pos  = g >> 2;
    int part = g & 3;
    const float4* xp = reinterpret_cast<const float4*>(x) + (size_t)pos * 16 + part * 4;
    int found = 0;
#pragma unroll
    for (int i = 0; i < 4; i++) {
        float4 v = xp[i];
        int base = part * 16 + i * 4;
        if (v.x > 0.5f) found = base;
        if (v.y > 0.5f) found = base + 1;
        if (v.z > 0.5f) found = base + 2;
        if (v.w > 0.5f) found = base + 3;
    }
    found = max(found, __shfl_xor_sync(0xFFFFFFFFu, found, 1));
    found = max(found, __shfl_xor_sync(0xFFFFFFFFu, found, 2));
    if (part == 0) g_sym[pos] = (unsigned short)found;
}

// ---------------------------------------------------------------------------
// Kernel 1: persistent clustered forward recurrence with DSMEM all-gather.
//   grid = 128 CTAs, cluster (8,1,1), 256 threads, dynamic SMEM 66688 B.
//   CTA rank r owns output states [64r, 64r+64); cluster cl owns 8 batch rows.
//   Warp g owns K-octant [64g, 64g+64); thread holds A[octant, {cp, cp+32}]
//   as 64 packed f32x2 registers. p kept UNscaled; rinv applied in epilogue.
// ---------------------------------------------------------------------------
__global__ void __cluster_dims__(CPC, 1, 1) __launch_bounds__(256, 1)
hmm_fwd_kernel(const float* __restrict__ A, const float* __restrict__ Bm,
               float* __restrict__ out)
{
    extern __shared__ char smem_raw[];
    float*  p0      = reinterpret_cast<float*>(smem_raw + SM_P);     // [2][RPC][NS]
    float (*part_sh)[RPC][NC] = reinterpret_cast<float(*)[RPC][NC]>(smem_raw + SM_PART);
    float (*B_sh)[NC]         = reinterpret_cast<float(*)[NC]>(smem_raw + SM_B);
    float*  lmax    = reinterpret_cast<float*>(smem_raw + SM_LMAX);  // [2][RPC][CPC][2]
    double* c_sh    = reinterpret_cast<double*>(smem_raw + SM_C);
    float*  rinv_sh = reinterpret_cast<float*>(smem_raw + SM_RINV);
    unsigned short* sym_sh = reinterpret_cast<unsigned short*>(smem_raw + SM_SYM);

    const int tid  = threadIdx.x;
    const int lane = tid & 31;
    const int warp = tid >> 5;
    const int c    = tid & 63;   // epilogue column within slice
    const int cp   = tid & 31;   // matmul column pair base
    const int g    = tid >> 5;   // K-octant == warp id

    unsigned int r_;
    asm("mov.u32 %0, %%cluster_ctarank;" : "=r"(r_));
    const int r    = (int)r_;
    const int cl   = (int)blockIdx.x / CPC;
    const int col0 = r * NC;

    const unsigned int smem_base = smem_u32(smem_raw);

    // Remote SMEM base addresses for all 8 cluster ranks (p and lmax regions)
    unsigned int p_rem[CPC];
#pragma unroll
    for (int rr = 0; rr < CPC; rr++)
        p_rem[rr] = mapa_sh(smem_base + SM_P, rr);
    const unsigned int lmax_rem = mapa_sh(smem_base + SM_LMAX, lane & 7);

    // ---- A slice into registers as packed f32x2 (constant all steps) ----
    unsigned long long a0[32], a1[32];
#pragma unroll
    for (int j = 0; j < 32; j++) {
        int k = g * 64 + 2 * j;
        float x00 = A[(size_t)k * NS + col0 + cp];
        float x01 = A[(size_t)(k + 1) * NS + col0 + cp];
        float x10 = A[(size_t)k * NS + col0 + cp + 32];
        float x11 = A[(size_t)(k + 1) * NS + col0 + cp + 32];
        a0[j] = pack2(x00, x01);
        a1[j] = pack2(x10, x11);
    }

    // ---- emission slice ----
    for (int i = tid; i < NM * NC; i += 256)
        B_sh[i >> 6][i & 63] = Bm[(size_t)(i >> 6) * NS + col0 + (i & 63)];

    if (tid < RPC) c_sh[tid] = 0.0;

    // ---- init (local, identical in every CTA): u0 = [B[s0][0], 0, ...] ----
    for (int i = tid; i < RPC * NS; i += 256) {
        int row = i >> 9, cc = i & 511;
        float v = 0.f;
        if (cc == 0) {
            int s0 = g_sym[(size_t)(cl * RPC + row) * TB];
            v = Bm[(size_t)s0 * NS];
        }
        p0[row * NS + cc] = v;   // buffer 0
    }
    for (int i = tid; i < RPC * CPC * 2; i += 256) {
        int row = i / (CPC * 2);
        int s0 = g_sym[(size_t)(cl * RPC + row) * TB];
        lmax[i] = Bm[(size_t)s0 * NS];   // buffer 0: every slot = global max
    }
    __syncthreads();
    asm volatile("barrier.cluster.arrive.aligned;" ::: "memory");
    asm volatile("barrier.cluster.wait.aligned;"   ::: "memory");

    int buf = 0;
    for (int t = 1; t < TB; t++) {
        // -- warp 7 prefetches this step's symbols (latency hidden by matmul)
        unsigned short symr = 0;
        if (warp == 7 && lane < RPC)
            symr = __ldg(&g_sym[(size_t)(cl * RPC + lane) * TB + t]);

        // -- matmul on UNscaled local p: part[g][row][{cp,cp+32}] --
        const float* pbase = p0 + buf * (RPC * NS);
#pragma unroll 1
        for (int row = 0; row < RPC; row += 2) {
            const ulonglong2* pp0 =
                reinterpret_cast<const ulonglong2*>(pbase + row * NS + g * 64);
            const ulonglong2* pp1 =
                reinterpret_cast<const ulonglong2*>(pbase + (row + 1) * NS + g * 64);
            unsigned long long acc00 = 0ull, acc01 = 0ull;
            unsigned long long acc10 = 0ull, acc11 = 0ull;
#pragma unroll
            for (int j4 = 0; j4 < 16; j4++) {
                ulonglong2 pv0 = pp0[j4];            // LDS.128 broadcast
                ulonglong2 pv1 = pp1[j4];
                ffma2(acc00, a0[2 * j4],     pv0.x);
                ffma2(acc01, a1[2 * j4],     pv0.x);
                ffma2(acc10, a0[2 * j4],     pv1.x);
                ffma2(acc11, a1[2 * j4],     pv1.x);
                ffma2(acc00, a0[2 * j4 + 1], pv0.y);
                ffma2(acc01, a1[2 * j4 + 1], pv0.y);
                ffma2(acc10, a0[2 * j4 + 1], pv1.y);
                ffma2(acc11, a1[2 * j4 + 1], pv1.y);
            }
            float2 s00 = unpack2(acc00), s01 = unpack2(acc01);
            float2 s10 = unpack2(acc10), s11 = unpack2(acc11);
            part_sh[g][row][cp]          = s00.x + s00.y;
            part_sh[g][row][cp + 32]     = s01.x + s01.y;
            part_sh[g][row + 1][cp]      = s10.x + s10.y;
            part_sh[g][row + 1][cp + 32] = s11.x + s11.y;
        }

        // -- warp 0: rinv + running log-scale from last step's lmax (off path)
        if (warp == 0 && lane < RPC) {
            const float4* la = reinterpret_cast<const float4*>(
                lmax + (buf * RPC + lane) * (CPC * 2));
            float4 m0 = la[0], m1 = la[1], m2 = la[2], m3 = la[3];
            float m = fmaxf(fmaxf(fmaxf(m0.x, m0.y), fmaxf(m0.z, m0.w)),
                            fmaxf(fmaxf(m1.x, m1.y), fmaxf(m1.z, m1.w)));
            m = fmaxf(m, fmaxf(fmaxf(fmaxf(m2.x, m2.y), fmaxf(m2.z, m2.w)),
                               fmaxf(fmaxf(m3.x, m3.y), fmaxf(m3.z, m3.w))));
            rinv_sh[lane] = 1.0f / m;
            c_sh[lane] += (double)logf(m);
        }
        if (warp == 7 && lane < RPC)
            sym_sh[lane] = symr;
        __syncthreads();

        // -- epilogue: reduce octants, scale, apply E, DSMEM all-gather --
        const int bufn = buf ^ 1;
        float hm[2];
#pragma unroll
        for (int h = 0; h < 2; h++) {
            const int row = (tid >> 6) + h * 4;
            float s = ((part_sh[0][row][c] + part_sh[1][row][c])
                     + (part_sh[2][row][c] + part_sh[3][row][c]))
                    + ((part_sh[4][row][c] + part_sh[5][row][c])
                     + (part_sh[6][row][c] + part_sh[7][row][c]));
            float u = s * rinv_sh[row] * B_sh[sym_sh[row]][c];
            unsigned int off = (unsigned int)(((bufn * RPC + row) * NS) + col0 + c) * 4u;
#pragma unroll
            for (int rr = 0; rr < CPC; rr++)
                st_cluster_f32(p_rem[rr] + off, u);
            hm[h] = warp_max_f32(u);                // half-slice max, all lanes
        }
        // lanes 0..7 broadcast this CTA's half-maxes to every CTA's lmax[bufn]
        if (lane < CPC) {
            const int half = warp & 1;
            const int rw0  = warp >> 1;
            unsigned int o0 = (unsigned int)((((bufn * RPC + rw0)     * CPC + r) * 2 + half)) * 4u;
            unsigned int o1 = (unsigned int)((((bufn * RPC + rw0 + 4) * CPC + r) * 2 + half)) * 4u;
            st_cluster_f32(lmax_rem + o0, hm[0]);
            st_cluster_f32(lmax_rem + o1, hm[1]);
        }

        asm volatile("barrier.cluster.arrive.aligned;" ::: "memory");
        asm volatile("barrier.cluster.wait.aligned;"   ::: "memory");
        buf = bufn;
    }

    // ---- alpha_T = log(u_T) + C (each CTA writes its own column slice) ----
#pragma unroll
    for (int h = 0; h < 2; h++) {
        const int row = (tid >> 6) + h * 4;
        float u = p0[(buf * RPC + row) * NS + col0 + c];
        out[(size_t)(cl * RPC + row) * NS + col0 + c] =
            (float)((double)logf(u) + c_sh[row]);
    }
}

// ---------------------------------------------------------------------------
// Kernel 2: loglik[b] = log(sum_s exp(alpha - m) + S*eps) + m, one warp per row
// ---------------------------------------------------------------------------
__global__ void loglik_kernel(float* __restrict__ out) {
    const int b    = blockIdx.x;
    const int lane = threadIdx.x;
    const float* a = out + (size_t)b * NS;
    float v[16];
    float m = -3.0e38f;
#pragma unroll
    for (int i = 0; i < 16; i++) { v[i] = a[lane + i * 32]; m = fmaxf(m, v[i]); }
#pragma unroll
    for (int o = 16; o >= 1; o >>= 1) m = fmaxf(m, __shfl_xor_sync(0xFFFFFFFFu, m, o));
    float s = 0.f;
#pragma unroll
    for (int i = 0; i < 16; i++) s += expf(v[i] - m);
#pragma unroll
    for (int o = 16; o >= 1; o >>= 1) s += __shfl_xor_sync(0xFFFFFFFFu, s, o);
    if (lane == 0) out[NB * NS + b] = logf(s + 512.0f * 1e-16f) + m;
}

// ---------------------------------------------------------------------------
extern "C" void kernel_launch(void* const* d_in, const int* in_sizes, int n_in,
                              void* d_out, int out_size) {
    const float* x  = nullptr;
    const float* A  = nullptr;
    const float* Bm = nullptr;
    for (int i = 0; i < n_in; i++) {
        if      (in_sizes[i] == NB * TB * NM) x  = (const float*)d_in[i];
        else if (in_sizes[i] == NS * NS)      A  = (const float*)d_in[i];
        else if (in_sizes[i] == NM * NS)      Bm = (const float*)d_in[i];
    }
    if (!x  && n_in > 0) x  = (const float*)d_in[0];
    if (!A  && n_in > 1) A  = (const float*)d_in[1];
    if (!Bm && n_in > 2) Bm = (const float*)d_in[2];

    float* out = (float*)d_out;

    cudaFuncSetAttribute(hmm_fwd_kernel,
                         cudaFuncAttributeMaxDynamicSharedMemorySize, SM_TOTAL);

    extract_sym_kernel<<<(NB * TB * 4) / 256, 256>>>(x);
    hmm_fwd_kernel<<<NCL * CPC, 256, SM_TOTAL>>>(A, Bm, out);
    if (out_size >= NB * NS + NB)
        loglik_kernel<<<NB, 32>>>(out);
}

// round 8
// speedup vs baseline: 1.4131x; 1.0025x over previous
#include <cuda_runtime.h>
#include <math.h>

// Problem constants
#define TB   8192   // T
#define NB   128    // batch
#define NS   512    // states
#define NM   64     // symbols
#define NCL  16     // clusters (batch groups)
#define RPC  8      // batch rows per cluster
#define CPC  8      // CTAs per cluster (state slices)
#define NC   64     // state columns per CTA

// Dynamic SMEM layout (bytes)
#define SM_P     0            // p_sh   [2][RPC][NS]       32768
#define SM_PART  32768        // part_sh[8][RPC][NC]       16384
#define SM_B     49152        // B_sh   [NM][NC]           16384
#define SM_LMAX  65536        // lmax   [2][RPC][CPC][2]    1024
#define SM_C     66560        // c_sh   [RPC] double          64
#define SM_RINV  66624        // rinv   [RPC] float           32
#define SM_SYM   66656        // sym    [RPC] u16             16
#define SM_TOTAL 66688

// Static device scratch
__device__ unsigned short g_sym[NB * TB];            // 2 MB: symbol per (b,t)

// ---- packed fp32x2 / DSMEM helpers ----------------------------------------
__device__ __forceinline__ void ffma2(unsigned long long& acc,
                                      unsigned long long a,
                                      unsigned long long b) {
    asm("fma.rn.f32x2 %0, %1, %2, %0;" : "+l"(acc) : "l"(a), "l"(b));
}
__device__ __forceinline__ unsigned long long pack2(float x, float y) {
    unsigned long long r;
    asm("mov.b64 %0, {%1, %2};" : "=l"(r) : "f"(x), "f"(y));
    return r;
}
__device__ __forceinline__ float2 unpack2(unsigned long long v) {
    float2 r;
    asm("mov.b64 {%0, %1}, %2;" : "=f"(r.x), "=f"(r.y) : "l"(v));
    return r;
}
__device__ __forceinline__ unsigned int mapa_sh(unsigned int addr, unsigned int rank) {
    unsigned int d;
    asm("mapa.shared::cluster.u32 %0, %1, %2;" : "=r"(d) : "r"(addr), "r"(rank));
    return d;
}
__device__ __forceinline__ void st_cluster_f32(unsigned int addr, float v) {
    asm volatile("st.shared::cluster.f32 [%0], %1;" :: "r"(addr), "f"(v) : "memory");
}
__device__ __forceinline__ float warp_max_f32(float v) {
#pragma unroll
    for (int o = 16; o >= 1; o >>= 1)
        v = fmaxf(v, __shfl_xor_sync(0xFFFFFFFFu, v, o));
    return v;
}
__device__ __forceinline__ unsigned int smem_u32(const void* p) {
    unsigned int a;
    asm("{ .reg .u64 t; cvta.to.shared.u64 t, %1; cvt.u32.u64 %0, t; }"
        : "=r"(a) : "l"(p));
    return a;
}

// ---------------------------------------------------------------------------
// Kernel 0: collapse one-hot x[b,t,:] -> symbol index. 4 threads per position.
// ---------------------------------------------------------------------------
__global__ void extract_sym_kernel(const float* __restrict__ x) {
    int g = blockIdx.x * blockDim.x + threadIdx.x;
    int pos  = g >> 2;
    int part = g & 3;
    const float4* xp = reinterpret_cast<const float4*>(x) + (size_t)pos * 16 + part * 4;
    int found = 0;
#pragma unroll
    for (int i = 0; i < 4; i++) {
        float4 v = xp[i];
        int base = part * 16 + i * 4;
        if (v.x > 0.5f) found = base;
        if (v.y > 0.5f) found = base + 1;
        if (v.z > 0.5f) found = base + 2;
        if (v.w > 0.5f) found = base + 3;
    }
    found = max(found, __shfl_xor_sync(0xFFFFFFFFu, found, 1));
    found = max(found, __shfl_xor_sync(0xFFFFFFFFu, found, 2));
    if (part == 0) g_sym[pos] = (unsigned short)found;
}

// ---------------------------------------------------------------------------
// Kernel 1: persistent clustered forward recurrence with DSMEM all-gather.
//   grid = 128 CTAs, cluster (8,1,1), 256 threads, dynamic SMEM 66688 B.
//   CTA rank r owns output states [64r, 64r+64); cluster cl owns 8 batch rows.
//   Warp g owns K-octant [64g, 64g+64); thread holds A[octant, {cp, cp+32}]
//   as 64 packed f32x2 registers. p kept UNscaled; rinv applied in epilogue.
// ---------------------------------------------------------------------------
__global__ void __cluster_dims__(CPC, 1, 1) __launch_bounds__(256, 1)
hmm_fwd_kernel(const float* __restrict__ A, const float* __restrict__ Bm,
               float* __restrict__ out)
{
    extern __shared__ char smem_raw[];
    float*  p0      = reinterpret_cast<float*>(smem_raw + SM_P);     // [2][RPC][NS]
    float (*part_sh)[RPC][NC] = reinterpret_cast<float(*)[RPC][NC]>(smem_raw + SM_PART);
    float (*B_sh)[NC]         = reinterpret_cast<float(*)[NC]>(smem_raw + SM_B);
    float*  lmax    = reinterpret_cast<float*>(smem_raw + SM_LMAX);  // [2][RPC][CPC][2]
    double* c_sh    = reinterpret_cast<double*>(smem_raw + SM_C);
    float*  rinv_sh = reinterpret_cast<float*>(smem_raw + SM_RINV);
    unsigned short* sym_sh = reinterpret_cast<unsigned short*>(smem_raw + SM_SYM);

    const int tid  = threadIdx.x;
    const int lane = tid & 31;
    const int warp = tid >> 5;
    const int c    = tid & 63;   // epilogue column within slice
    const int cp   = tid & 31;   // matmul column pair base
    const int g    = tid >> 5;   // K-octant == warp id

    unsigned int r_;
    asm("mov.u32 %0, %%cluster_ctarank;" : "=r"(r_));
    const int r    = (int)r_;
    const int cl   = (int)blockIdx.x / CPC;
    const int col0 = r * NC;

    const unsigned int smem_base = smem_u32(smem_raw);

    // Remote SMEM base addresses for all 8 cluster ranks (p and lmax regions)
    unsigned int p_rem[CPC];
#pragma unroll
    for (int rr = 0; rr < CPC; rr++)
        p_rem[rr] = mapa_sh(smem_base + SM_P, rr);
    const unsigned int lmax_rem = mapa_sh(smem_base + SM_LMAX, lane & 7);

    // ---- A slice into registers as packed f32x2 (constant all steps) ----
    unsigned long long a0[32], a1[32];
#pragma unroll
    for (int j = 0; j < 32; j++) {
        int k = g * 64 + 2 * j;
        float x00 = A[(size_t)k * NS + col0 + cp];
        float x01 = A[(size_t)(k + 1) * NS + col0 + cp];
        float x10 = A[(size_t)k * NS + col0 + cp + 32];
        float x11 = A[(size_t)(k + 1) * NS + col0 + cp + 32];
        a0[j] = pack2(x00, x01);
        a1[j] = pack2(x10, x11);
    }

    // ---- emission slice ----
    for (int i = tid; i < NM * NC; i += 256)
        B_sh[i >> 6][i & 63] = Bm[(size_t)(i >> 6) * NS + col0 + (i & 63)];

    if (tid < RPC) c_sh[tid] = 0.0;

    // ---- init (local, identical in every CTA): u0 = [B[s0][0], 0, ...] ----
    for (int i = tid; i < RPC * NS; i += 256) {
        int row = i >> 9, cc = i & 511;
        float v = 0.f;
        if (cc == 0) {
            int s0 = g_sym[(size_t)(cl * RPC + row) * TB];
            v = Bm[(size_t)s0 * NS];
        }
        p0[row * NS + cc] = v;   // buffer 0
    }
    for (int i = tid; i < RPC * CPC * 2; i += 256) {
        int row = i / (CPC * 2);
        int s0 = g_sym[(size_t)(cl * RPC + row) * TB];
        lmax[i] = Bm[(size_t)s0 * NS];   // buffer 0: every slot = global max
    }
    __syncthreads();
    asm volatile("barrier.cluster.arrive.aligned;" ::: "memory");
    asm volatile("barrier.cluster.wait.aligned;"   ::: "memory");

    int buf = 0;
    for (int t = 1; t < TB; t++) {
        // -- warp 7 prefetches this step's symbols (latency hidden by matmul)
        unsigned short symr = 0;
        if (warp == 7 && lane < RPC)
            symr = __ldg(&g_sym[(size_t)(cl * RPC + lane) * TB + t]);

        // -- matmul on UNscaled local p: part[g][row][{cp,cp+32}] --
        const float* pbase = p0 + buf * (RPC * NS);
#pragma unroll 1
        for (int row = 0; row < RPC; row += 2) {
            const ulonglong2* pp0 =
                reinterpret_cast<const ulonglong2*>(pbase + row * NS + g * 64);
            const ulonglong2* pp1 =
                reinterpret_cast<const ulonglong2*>(pbase + (row + 1) * NS + g * 64);
            unsigned long long acc00 = 0ull, acc01 = 0ull;
            unsigned long long acc10 = 0ull, acc11 = 0ull;
#pragma unroll
            for (int j4 = 0; j4 < 16; j4++) {
                ulonglong2 pv0 = pp0[j4];            // LDS.128 broadcast
                ulonglong2 pv1 = pp1[j4];
                ffma2(acc00, a0[2 * j4],     pv0.x);
                ffma2(acc01, a1[2 * j4],     pv0.x);
                ffma2(acc10, a0[2 * j4],     pv1.x);
                ffma2(acc11, a1[2 * j4],     pv1.x);
                ffma2(acc00, a0[2 * j4 + 1], pv0.y);
                ffma2(acc01, a1[2 * j4 + 1], pv0.y);
                ffma2(acc10, a0[2 * j4 + 1], pv1.y);
                ffma2(acc11, a1[2 * j4 + 1], pv1.y);
            }
            float2 s00 = unpack2(acc00), s01 = unpack2(acc01);
            float2 s10 = unpack2(acc10), s11 = unpack2(acc11);
            part_sh[g][row][cp]          = s00.x + s00.y;
            part_sh[g][row][cp + 32]     = s01.x + s01.y;
            part_sh[g][row + 1][cp]      = s10.x + s10.y;
            part_sh[g][row + 1][cp + 32] = s11.x + s11.y;
        }

        // -- warp 0: rinv + running log-scale from last step's lmax (off path)
        if (warp == 0 && lane < RPC) {
            const float4* la = reinterpret_cast<const float4*>(
                lmax + (buf * RPC + lane) * (CPC * 2));
            float4 m0 = la[0], m1 = la[1], m2 = la[2], m3 = la[3];
            float m = fmaxf(fmaxf(fmaxf(m0.x, m0.y), fmaxf(m0.z, m0.w)),
                            fmaxf(fmaxf(m1.x, m1.y), fmaxf(m1.z, m1.w)));
            m = fmaxf(m, fmaxf(fmaxf(fmaxf(m2.x, m2.y), fmaxf(m2.z, m2.w)),
                               fmaxf(fmaxf(m3.x, m3.y), fmaxf(m3.z, m3.w))));
            rinv_sh[lane] = 1.0f / m;
            c_sh[lane] += (double)logf(m);
        }
        if (warp == 7 && lane < RPC)
            sym_sh[lane] = symr;
        __syncthreads();

        // -- epilogue: reduce octants, scale, apply E, DSMEM all-gather --
        const int bufn = buf ^ 1;
        float hm[2];
#pragma unroll
        for (int h = 0; h < 2; h++) {
            const int row = (tid >> 6) + h * 4;
            float s = ((part_sh[0][row][c] + part_sh[1][row][c])
                     + (part_sh[2][row][c] + part_sh[3][row][c]))
                    + ((part_sh[4][row][c] + part_sh[5][row][c])
                     + (part_sh[6][row][c] + part_sh[7][row][c]));
            float u = s * rinv_sh[row] * B_sh[sym_sh[row]][c];
            unsigned int off = (unsigned int)(((bufn * RPC + row) * NS) + col0 + c) * 4u;
#pragma unroll
            for (int rr = 0; rr < CPC; rr++)
                st_cluster_f32(p_rem[rr] + off, u);
            hm[h] = warp_max_f32(u);                // half-slice max, all lanes
        }
        // lanes 0..7 broadcast this CTA's half-maxes to every CTA's lmax[bufn]
        if (lane < CPC) {
            const int half = warp & 1;
            const int rw0  = warp >> 1;
            unsigned int o0 = (unsigned int)((((bufn * RPC + rw0)     * CPC + r) * 2 + half)) * 4u;
            unsigned int o1 = (unsigned int)((((bufn * RPC + rw0 + 4) * CPC + r) * 2 + half)) * 4u;
            st_cluster_f32(lmax_rem + o0, hm[0]);
            st_cluster_f32(lmax_rem + o1, hm[1]);
        }

        asm volatile("barrier.cluster.arrive.aligned;" ::: "memory");
        asm volatile("barrier.cluster.wait.aligned;"   ::: "memory");
        buf = bufn;
    }

    // ---- alpha_T = log(u_T) + C (each CTA writes its own column slice) ----
#pragma unroll
    for (int h = 0; h < 2; h++) {
        const int row = (tid >> 6) + h * 4;
        float u = p0[(buf * RPC + row) * NS + col0 + c];
        out[(size_t)(cl * RPC + row) * NS + col0 + c] =
            (float)((double)logf(u) + c_sh[row]);
    }
}

// ---------------------------------------------------------------------------
// Kernel 2: loglik[b] = log(sum_s exp(alpha - m) + S*eps) + m, one warp per row
// ---------------------------------------------------------------------------
__global__ void loglik_kernel(float* __restrict__ out) {
    const int b    = blockIdx.x;
    const int lane = threadIdx.x;
    const float* a = out + (size_t)b * NS;
    float v[16];
    float m = -3.0e38f;
#pragma unroll
    for (int i = 0; i < 16; i++) { v[i] = a[lane + i * 32]; m = fmaxf(m, v[i]); }
#pragma unroll
    for (int o = 16; o >= 1; o >>= 1) m = fmaxf(m, __shfl_xor_sync(0xFFFFFFFFu, m, o));
    float s = 0.f;
#pragma unroll
    for (int i = 0; i < 16; i++) s += expf(v[i] - m);
#pragma unroll
    for (int o = 16; o >= 1; o >>= 1) s += __shfl_xor_sync(0xFFFFFFFFu, s, o);
    if (lane == 0) out[NB * NS + b] = logf(s + 512.0f * 1e-16f) + m;
}

// ---------------------------------------------------------------------------
extern "C" void kernel_launch(void* const* d_in, const int* in_sizes, int n_in,
                              void* d_out, int out_size) {
    const float* x  = nullptr;
    const float* A  = nullptr;
    const float* Bm = nullptr;
    for (int i = 0; i < n_in; i++) {
        if      (in_sizes[i] == NB * TB * NM) x  = (const float*)d_in[i];
        else if (in_sizes[i] == NS * NS)      A  = (const float*)d_in[i];
        else if (in_sizes[i] == NM * NS)      Bm = (const float*)d_in[i];
    }
    if (!x  && n_in > 0) x  = (const float*)d_in[0];
    if (!A  && n_in > 1) A  = (const float*)d_in[1];
    if (!Bm && n_in > 2) Bm = (const float*)d_in[2];

    float* out = (float*)d_out;

    cudaFuncSetAttribute(hmm_fwd_kernel,
                         cudaFuncAttributeMaxDynamicSharedMemorySize, SM_TOTAL);

    extract_sym_kernel<<<(NB * TB * 4) / 256, 256>>>(x);
    hmm_fwd_kernel<<<NCL * CPC, 256, SM_TOTAL>>>(A, Bm, out);
    if (out_size >= NB * NS + NB)
        loglik_kernel<<<NB, 32>>>(out);
}

// round 9
// speedup vs baseline: 2.4859x; 1.7592x over previous
#include <cuda_runtime.h>
#include <math.h>
#include <stdint.h>

// Problem constants
#define TB   8192   // T
#define NB   128    // batch
#define NS   512    // states
#define NM   64     // symbols
#define NCL  16     // clusters (batch groups)
#define RPC  8      // batch rows per cluster
#define CPC  8      // CTAs per cluster (state slices)
#define NC   64     // state columns per CTA
#define RSW  260    // p row stride in 32-bit words (256 data + 4 pad -> conflict-free)

// Dynamic SMEM layout (bytes)
#define SM_P     0            // uint32 p_w [2][RPC][RSW]   16640 (bf16 pairs)
#define SM_PART  16640        // float  part[8][64][8]      16384
#define SM_B     33024        // float  B_sh[NM][NC]        16384
#define SM_LMAX  49408        // float  lmax[2][64][8]       4096
#define SM_C     53504        // double c_sh[RPC]              64
#define SM_SYM   53568        // u16    sym [RPC]              16
#define SM_TOTAL 53600

// Static device scratch
__device__ unsigned short g_sym[NB * TB];            // 2 MB: symbol per (b,t)

// ---- helpers ---------------------------------------------------------------
__device__ __forceinline__ uint32_t bf16x2(float hi, float lo) {
    uint32_t d;
    asm("cvt.rn.bf16x2.f32 %0, %1, %2;" : "=r"(d) : "f"(hi), "f"(lo));
    return d;
}
__device__ __forceinline__ void mma16816(float* d, const uint32_t* a,
                                         uint32_t b0, uint32_t b1) {
    asm("mma.sync.aligned.m16n8k16.row.col.f32.bf16.bf16.f32 "
        "{%0,%1,%2,%3}, {%4,%5,%6,%7}, {%8,%9}, {%0,%1,%2,%3};"
        : "+f"(d[0]), "+f"(d[1]), "+f"(d[2]), "+f"(d[3])
        : "r"(a[0]), "r"(a[1]), "r"(a[2]), "r"(a[3]), "r"(b0), "r"(b1));
}
__device__ __forceinline__ uint32_t mapa_sh(uint32_t addr, uint32_t rank) {
    uint32_t d;
    asm("mapa.shared::cluster.u32 %0, %1, %2;" : "=r"(d) : "r"(addr), "r"(rank));
    return d;
}
__device__ __forceinline__ void st_cluster32(uint32_t addr, uint32_t v) {
    asm volatile("st.shared::cluster.u32 [%0], %1;" :: "r"(addr), "r"(v) : "memory");
}
__device__ __forceinline__ uint32_t smem_u32(const void* p) {
    uint32_t a;
    asm("{ .reg .u64 t; cvta.to.shared.u64 t, %1; cvt.u32.u64 %0, t; }"
        : "=r"(a) : "l"(p));
    return a;
}

// ---------------------------------------------------------------------------
// Kernel 0: collapse one-hot x[b,t,:] -> symbol index. 4 threads per position.
// ---------------------------------------------------------------------------
__global__ void extract_sym_kernel(const float* __restrict__ x) {
    int g = blockIdx.x * blockDim.x + threadIdx.x;
    int pos  = g >> 2;
    int part = g & 3;
    const float4* xp = reinterpret_cast<const float4*>(x) + (size_t)pos * 16 + part * 4;
    int found = 0;
#pragma unroll
    for (int i = 0; i < 4; i++) {
        float4 v = xp[i];
        int base = part * 16 + i * 4;
        if (v.x > 0.5f) found = base;
        if (v.y > 0.5f) found = base + 1;
        if (v.z > 0.5f) found = base + 2;
        if (v.w > 0.5f) found = base + 3;
    }
    found = max(found, __shfl_xor_sync(0xFFFFFFFFu, found, 1));
    found = max(found, __shfl_xor_sync(0xFFFFFFFFu, found, 2));
    if (part == 0) g_sym[pos] = (unsigned short)found;
}

// ---------------------------------------------------------------------------
// Kernel 1: persistent clustered forward recurrence, bf16 HMMA + fp32 accum.
//   grid = 128 CTAs, cluster (8,1,1), 256 threads.
//   CTA rank r owns output states [64r, 64r+64) (4 m16-tiles); N = 8 batch rows.
//   Warp w owns K-octant [64w, 64w+64) (4 k16-chunks). A-frags in 64 regs.
//   p stored as bf16 pairs (k-consecutive) = ready-made B-fragments.
// ---------------------------------------------------------------------------
__global__ void __cluster_dims__(CPC, 1, 1) __launch_bounds__(256, 1)
hmm_fwd_kernel(const float* __restrict__ A, const float* __restrict__ Bm,
               float* __restrict__ out)
{
    extern __shared__ char smem_raw[];
    uint32_t* p_w   = reinterpret_cast<uint32_t*>(smem_raw + SM_P);    // [2][RPC][RSW]
    float*    part  = reinterpret_cast<float*>(smem_raw + SM_PART);    // [8][64][8]
    float*    B_sh  = reinterpret_cast<float*>(smem_raw + SM_B);       // [NM][NC]
    float*    lmax  = reinterpret_cast<float*>(smem_raw + SM_LMAX);    // [2][64][8]
    double*   c_sh  = reinterpret_cast<double*>(smem_raw + SM_C);
    unsigned short* sym_sh = reinterpret_cast<unsigned short*>(smem_raw + SM_SYM);

    const int tid  = threadIdx.x;
    const int lane = tid & 31;
    const int warp = tid >> 5;
    const int gid  = lane >> 2;   // mma group id (0..7)
    const int tig  = lane & 3;    // thread in group

    uint32_t r_;
    asm("mov.u32 %0, %%cluster_ctarank;" : "=r"(r_));
    const int r    = (int)r_;
    const int cl   = (int)blockIdx.x / CPC;
    const int col0 = r * NC;

    const uint32_t smem_base = smem_u32(smem_raw);
    uint32_t p_rem[CPC], lmax_rem[CPC];
#pragma unroll
    for (int rr = 0; rr < CPC; rr++) {
        p_rem[rr]    = mapa_sh(smem_base + SM_P, rr);
        lmax_rem[rr] = mapa_sh(smem_base + SM_LMAX, rr);
    }

    // ---- A fragments (constant): areg[mt][kc][4], bf16 pairs over k ----
    // Aop[m][k] = A_global[k][col0 + mt*16 + m]; m16n8k16 row.col layout.
    uint32_t areg[4][4][4];
#pragma unroll
    for (int mt = 0; mt < 4; mt++)
#pragma unroll
    for (int kc = 0; kc < 4; kc++) {
        int m0 = col0 + mt * 16 + gid;
        int k0 = warp * 64 + kc * 16 + tig * 2;
        const float* A0 = A + (size_t)k0 * NS;
        areg[mt][kc][0] = bf16x2(A0[NS + m0],          A0[m0]);
        areg[mt][kc][1] = bf16x2(A0[NS + m0 + 8],      A0[m0 + 8]);
        areg[mt][kc][2] = bf16x2(A0[9 * NS + m0],      A0[8 * NS + m0]);
        areg[mt][kc][3] = bf16x2(A0[9 * NS + m0 + 8],  A0[8 * NS + m0 + 8]);
    }

    // ---- emission slice (fp32) ----
    for (int i = tid; i < NM * NC; i += 256)
        B_sh[(i >> 6) * NC + (i & 63)] = Bm[(size_t)(i >> 6) * NS + col0 + (i & 63)];

    if (tid < RPC) c_sh[tid] = 0.0;

    // ---- init buffer 0: p[b][k] = (k==0) ? B[sym0][0] : 0, as bf16 pairs ----
    for (int i = tid; i < RPC * RSW; i += 256) {
        int b = i / RSW, w = i % RSW;
        uint32_t v = 0;
        if (w == 0) {
            int s0 = g_sym[(size_t)(cl * RPC + b) * TB];
            v = bf16x2(0.0f, Bm[(size_t)s0 * NS]);   // lo = k0 value
        }
        p_w[b * RSW + w] = v;                        // buffer 0
    }
    for (int i = tid; i < 64 * RPC; i += 256) {
        int b = i & 7;
        int s0 = g_sym[(size_t)(cl * RPC + b) * TB];
        lmax[i] = Bm[(size_t)s0 * NS];               // buffer 0: all slots = true max
    }
    __syncthreads();
    asm volatile("barrier.cluster.arrive.aligned;" ::: "memory");
    asm volatile("barrier.cluster.wait.aligned;"   ::: "memory");

    int buf = 0;
    for (int t = 1; t < TB; t++) {
        // -- warp 7: prefetch this step's symbols into sym_sh (read post-sync)
        if (warp == 7 && lane < RPC)
            sym_sh[lane] = g_sym[(size_t)(cl * RPC + lane) * TB + t];

        // -- every warp: rinv for b = lane&7 from lmax[buf] (broadcast LDS) --
        float rinv;
        {
            const float* lm = lmax + buf * 512;
            float mx = lm[(lane >> 3) * 8 + (lane & 7)];
#pragma unroll
            for (int j = 1; j < 16; j++)
                mx = fmaxf(mx, lm[((lane >> 3) + 4 * j) * 8 + (lane & 7)]);
            mx = fmaxf(mx, __shfl_xor_sync(0xFFFFFFFFu, mx, 8));
            mx = fmaxf(mx, __shfl_xor_sync(0xFFFFFFFFu, mx, 16));
            rinv = 1.0f / mx;
            if (warp == 0 && lane < RPC) c_sh[lane] += (double)logf(mx);
        }

        // -- B fragments: p words ARE the fragments (b = gid, k-octant = warp)
        const uint32_t* pb = p_w + buf * (RPC * RSW);
        uint32_t bf0[4], bf1[4];
#pragma unroll
        for (int kc = 0; kc < 4; kc++) {
            int w0 = gid * RSW + warp * 32 + kc * 8 + tig;
            bf0[kc] = pb[w0];
            bf1[kc] = pb[w0 + 4];
        }

        // -- 16 HMMA: D[m=64 states, n=8 rows] partial over this K-octant --
        float d[4][4];
#pragma unroll
        for (int mt = 0; mt < 4; mt++) {
            d[mt][0] = 0.f; d[mt][1] = 0.f; d[mt][2] = 0.f; d[mt][3] = 0.f;
#pragma unroll
            for (int kc = 0; kc < 4; kc++)
                mma16816(d[mt], areg[mt][kc], bf0[kc], bf1[kc]);
        }
        // store partials: part[warp][m][n]
#pragma unroll
        for (int mt = 0; mt < 4; mt++) {
            int m = mt * 16 + gid;
            *reinterpret_cast<float2*>(part + (warp * 64 + m) * 8 + 2 * tig) =
                make_float2(d[mt][0], d[mt][1]);
            *reinterpret_cast<float2*>(part + (warp * 64 + m + 8) * 8 + 2 * tig) =
                make_float2(d[mt][2], d[mt][3]);
        }
        __syncthreads();

        // -- epilogue: thread -> (b = tid&7, s' pair s0, s0+1) --
        const int bufn = buf ^ 1;
        {
            const int b  = tid & 7;
            const int s0 = (tid >> 3) * 2;
            float u0, u1;
            {
                const float* pp = part + s0 * 8 + b;
                float a0 = pp[0 * 512] + pp[1 * 512];
                float a1 = pp[2 * 512] + pp[3 * 512];
                float a2 = pp[4 * 512] + pp[5 * 512];
                float a3 = pp[6 * 512] + pp[7 * 512];
                u0 = (a0 + a1) + (a2 + a3);
                const float* pq = part + (s0 + 1) * 8 + b;
                float b0 = pq[0 * 512] + pq[1 * 512];
                float b1 = pq[2 * 512] + pq[3 * 512];
                float b2 = pq[4 * 512] + pq[5 * 512];
                float b3 = pq[6 * 512] + pq[7 * 512];
                u1 = (b0 + b1) + (b2 + b3);
            }
            const int sy = sym_sh[b];
            u0 = u0 * rinv * B_sh[sy * NC + s0];
            u1 = u1 * rinv * B_sh[sy * NC + s0 + 1];
            uint32_t pw = bf16x2(u1, u0);            // lo = s0
            uint32_t off = (uint32_t)((bufn * RPC + b) * RSW + ((col0 + s0) >> 1)) * 4u;
#pragma unroll
            for (int rr = 0; rr < CPC; rr++)
                st_cluster32(p_rem[rr] + off, pw);

            // per-b max over this warp's s' slice; broadcast to all ranks
            float wm = fmaxf(u0, u1);
            wm = fmaxf(wm, __shfl_xor_sync(0xFFFFFFFFu, wm, 8));
            wm = fmaxf(wm, __shfl_xor_sync(0xFFFFFFFFu, wm, 16));
            if (lane < 8) {
                uint32_t lo = (uint32_t)((bufn * 64 + r * 8 + warp) * 8 + lane) * 4u;
#pragma unroll
                for (int rr = 0; rr < CPC; rr++)
                    st_cluster32(lmax_rem[rr] + lo, __float_as_uint(wm));
            }
        }
        asm volatile("barrier.cluster.arrive.aligned;" ::: "memory");
        asm volatile("barrier.cluster.wait.aligned;"   ::: "memory");
        buf = bufn;
    }

    // ---- alpha_T = log(u_T) + C (unpack bf16 pair) ----
    {
        const int b  = tid & 7;
        const int s0 = (tid >> 3) * 2;
        uint32_t pw = p_w[(buf * RPC + b) * RSW + ((col0 + s0) >> 1)];
        float u0 = __uint_as_float(pw << 16);
        float u1 = __uint_as_float(pw & 0xFFFF0000u);
        double cc = c_sh[b];
        out[(size_t)(cl * RPC + b) * NS + col0 + s0]     = (float)((double)logf(u0) + cc);
        out[(size_t)(cl * RPC + b) * NS + col0 + s0 + 1] = (float)((double)logf(u1) + cc);
    }
}

// ---------------------------------------------------------------------------
// Kernel 2: loglik[b] = log(sum_s exp(alpha - m) + S*eps) + m, one warp per row
// ---------------------------------------------------------------------------
__global__ void loglik_kernel(float* __restrict__ out) {
    const int b    = blockIdx.x;
    const int lane = threadIdx.x;
    const float* a = out + (size_t)b * NS;
    float v[16];
    float m = -3.0e38f;
#pragma unroll
    for (int i = 0; i < 16; i++) { v[i] = a[lane + i * 32]; m = fmaxf(m, v[i]); }
#pragma unroll
    for (int o = 16; o >= 1; o >>= 1) m = fmaxf(m, __shfl_xor_sync(0xFFFFFFFFu, m, o));
    float s = 0.f;
#pragma unroll
    for (int i = 0; i < 16; i++) s += expf(v[i] - m);
#pragma unroll
    for (int o = 16; o >= 1; o >>= 1) s += __shfl_xor_sync(0xFFFFFFFFu, s, o);
    if (lane == 0) out[NB * NS + b] = logf(s + 512.0f * 1e-16f) + m;
}

// ---------------------------------------------------------------------------
extern "C" void kernel_launch(void* const* d_in, const int* in_sizes, int n_in,
                              void* d_out, int out_size) {
    const float* x  = nullptr;
    const float* A  = nullptr;
    const float* Bm = nullptr;
    for (int i = 0; i < n_in; i++) {
        if      (in_sizes[i] == NB * TB * NM) x  = (const float*)d_in[i];
        else if (in_sizes[i] == NS * NS)      A  = (const float*)d_in[i];
        else if (in_sizes[i] == NM * NS)      Bm = (const float*)d_in[i];
    }
    if (!x  && n_in > 0) x  = (const float*)d_in[0];
    if (!A  && n_in > 1) A  = (const float*)d_in[1];
    if (!Bm && n_in > 2) Bm = (const float*)d_in[2];

    float* out = (float*)d_out;

    cudaFuncSetAttribute(hmm_fwd_kernel,
                         cudaFuncAttributeMaxDynamicSharedMemorySize, SM_TOTAL);

    extract_sym_kernel<<<(NB * TB * 4) / 256, 256>>>(x);
    hmm_fwd_kernel<<<NCL * CPC, 256, SM_TOTAL>>>(A, Bm, out);
    if (out_size >= NB * NS + NB)
        loglik_kernel<<<NB, 32>>>(out);
}

// round 10
// speedup vs baseline: 3.1546x; 1.2690x over previous
#include <cuda_runtime.h>
#include <math.h>
#include <stdint.h>

// Problem constants
#define TB   8192   // T
#define NB   128    // batch
#define NS   512    // states
#define NM   64     // symbols
#define NCL  16     // clusters (batch groups)
#define RPC  8      // batch rows per cluster
#define CPC  8      // CTAs per cluster (state slices)
#define NC   64     // state columns per CTA
#define RSW  260    // p row stride in 32-bit words (256 data + 4 pad)
#define PSD  76     // part s-dim pad (conflict-free ST + LD)

// Static device scratch
__device__ unsigned short g_sym[NB * TB];            // 2 MB: symbol per (b,t)

// ---- helpers ---------------------------------------------------------------
__device__ __forceinline__ uint32_t bf16x2(float hi, float lo) {
    uint32_t d;
    asm("cvt.rn.bf16x2.f32 %0, %1, %2;" : "=r"(d) : "f"(hi), "f"(lo));
    return d;
}
__device__ __forceinline__ void mma16816(float* d, const uint32_t* a,
                                         uint32_t b0, uint32_t b1) {
    asm("mma.sync.aligned.m16n8k16.row.col.f32.bf16.bf16.f32 "
        "{%0,%1,%2,%3}, {%4,%5,%6,%7}, {%8,%9}, {%0,%1,%2,%3};"
        : "+f"(d[0]), "+f"(d[1]), "+f"(d[2]), "+f"(d[3])
        : "r"(a[0]), "r"(a[1]), "r"(a[2]), "r"(a[3]), "r"(b0), "r"(b1));
}
__device__ __forceinline__ uint32_t mapa_sh(uint32_t addr, uint32_t rank) {
    uint32_t d;
    asm("mapa.shared::cluster.u32 %0, %1, %2;" : "=r"(d) : "r"(addr), "r"(rank));
    return d;
}
__device__ __forceinline__ void st_cluster32(uint32_t addr, uint32_t v) {
    asm volatile("st.shared::cluster.u32 [%0], %1;" :: "r"(addr), "r"(v) : "memory");
}
__device__ __forceinline__ uint32_t smem_u32(const void* p) {
    uint32_t a;
    asm("{ .reg .u64 t; cvta.to.shared.u64 t, %1; cvt.u32.u64 %0, t; }"
        : "=r"(a) : "l"(p));
    return a;
}

// ---------------------------------------------------------------------------
// Kernel 0: collapse one-hot x[b,t,:] -> symbol index. 4 threads per position.
// ---------------------------------------------------------------------------
__global__ void extract_sym_kernel(const float* __restrict__ x) {
    int g = blockIdx.x * blockDim.x + threadIdx.x;
    int pos  = g >> 2;
    int part = g & 3;
    const float4* xp = reinterpret_cast<const float4*>(x) + (size_t)pos * 16 + part * 4;
    int found = 0;
#pragma unroll
    for (int i = 0; i < 4; i++) {
        float4 v = xp[i];
        int base = part * 16 + i * 4;
        if (v.x > 0.5f) found = base;
        if (v.y > 0.5f) found = base + 1;
        if (v.z > 0.5f) found = base + 2;
        if (v.w > 0.5f) found = base + 3;
    }
    found = max(found, __shfl_xor_sync(0xFFFFFFFFu, found, 1));
    found = max(found, __shfl_xor_sync(0xFFFFFFFFu, found, 2));
    if (part == 0) g_sym[pos] = (unsigned short)found;
}

// ---------------------------------------------------------------------------
// Kernel 1: persistent clustered forward recurrence, bf16 HMMA + fp32 accum.
//   grid = 128 CTAs, cluster (8,1,1), 256 threads, static SMEM ~38 KB.
//   CTA rank r owns output states [64r, 64r+64); cluster cl owns 8 batch rows.
//   MMA phase:  warp w -> (mt = w&3 : m16 tile, kh = w>>2 : K-half of 256).
//               16 HMMA over 4 interleaved accumulator chains; 2-way K reduce.
//   Epilogue:   warp w -> batch row b=w, lane -> state pair (2*lane, 2*lane+1).
// ---------------------------------------------------------------------------
__global__ void __cluster_dims__(CPC, 1, 1) __launch_bounds__(256, 1)
hmm_fwd_kernel(const float* __restrict__ A, const float* __restrict__ Bm,
               float* __restrict__ out)
{
    __shared__ uint32_t p_w[2][RPC][RSW];        // bf16-pair p, double buffered
    __shared__ float    part[2][RPC][PSD];       // K-half partials [kh][n][m]
    __shared__ float    B_sh[NM][NC];            // emission slice
    __shared__ float    lmax[2][RPC][8];         // per-CTA slice maxes
    __shared__ double   c_sh[RPC];               // running log-scale per row

    const int tid  = threadIdx.x;
    const int lane = tid & 31;
    const int warp = tid >> 5;
    const int gid  = lane >> 2;   // mma group id (0..7)
    const int tig  = lane & 3;    // thread in group
    const int mt   = warp & 3;    // m16 tile
    const int kh   = warp >> 2;   // K-half

    uint32_t r_;
    asm("mov.u32 %0, %%cluster_ctarank;" : "=r"(r_));
    const int r    = (int)r_;
    const int cl   = (int)blockIdx.x / CPC;
    const int col0 = r * NC;

    const uint32_t p_base    = smem_u32(&p_w[0][0][0]);
    const uint32_t lmax_base = smem_u32(&lmax[0][0][0]);
    uint32_t p_rem[CPC], lmax_rem[CPC];
#pragma unroll
    for (int rr = 0; rr < CPC; rr++) {
        p_rem[rr]    = mapa_sh(p_base, rr);
        lmax_rem[rr] = mapa_sh(lmax_base, rr);
    }

    // ---- A fragments (constant): areg[16 kc][4], this warp's (mt, kh) ----
    uint32_t areg[16][4];
#pragma unroll
    for (int kc = 0; kc < 16; kc++) {
        int m0 = col0 + mt * 16 + gid;
        int k0 = kh * 256 + kc * 16 + tig * 2;
        const float* A0 = A + (size_t)k0 * NS;
        areg[kc][0] = bf16x2(A0[NS + m0],          A0[m0]);
        areg[kc][1] = bf16x2(A0[NS + m0 + 8],      A0[m0 + 8]);
        areg[kc][2] = bf16x2(A0[9 * NS + m0],      A0[8 * NS + m0]);
        areg[kc][3] = bf16x2(A0[9 * NS + m0 + 8],  A0[8 * NS + m0 + 8]);
    }

    // ---- emission slice (fp32) ----
    for (int i = tid; i < NM * NC; i += 256)
        B_sh[i >> 6][i & 63] = Bm[(size_t)(i >> 6) * NS + col0 + (i & 63)];

    if (tid < RPC) c_sh[tid] = 0.0;

    // ---- init buffer 0: p[b][k] = (k==0) ? B[sym0][0] : 0 (bf16 pairs) ----
    for (int i = tid; i < RPC * RSW; i += 256) {
        int b = i / RSW, w = i % RSW;
        uint32_t v = 0;
        if (w == 0) {
            int s0 = g_sym[(size_t)(cl * RPC + b) * TB];
            v = bf16x2(0.0f, Bm[(size_t)s0 * NS]);
        }
        p_w[0][b][w] = v;
    }
    if (tid < RPC * 8) {
        int b = tid >> 3;
        int s0 = g_sym[(size_t)(cl * RPC + b) * TB];
        lmax[0][b][tid & 7] = Bm[(size_t)s0 * NS];
    }
    __syncthreads();
    asm volatile("barrier.cluster.arrive.aligned;" ::: "memory");
    asm volatile("barrier.cluster.wait.aligned;"   ::: "memory");

    int buf = 0;
    for (int t = 1; t < TB; t++) {
        // -- symbol for this warp's epilogue row (L2 broadcast, hidden) --
        const unsigned short symw = __ldg(&g_sym[(size_t)(cl * RPC + warp) * TB + t]);

        // -- B fragments for (b = gid, K-half kh) --
        const uint32_t (*pb)[RSW] = p_w[buf];
        uint32_t bf0[16], bf1[16];
#pragma unroll
        for (int kc = 0; kc < 16; kc++) {
            int w0 = gid * RSW + kh * 128 + kc * 8 + tig;
            bf0[kc] = (&pb[0][0])[w0];
            bf1[kc] = (&pb[0][0])[w0 + 4];
        }

        // -- 16 HMMA over 4 interleaved accumulator chains --
        float acc[4][4];
#pragma unroll
        for (int j = 0; j < 4; j++) { acc[j][0] = acc[j][1] = acc[j][2] = acc[j][3] = 0.f; }
#pragma unroll
        for (int kc = 0; kc < 16; kc++)
            mma16816(acc[kc & 3], areg[kc], bf0[kc], bf1[kc]);
        float d0 = (acc[0][0] + acc[1][0]) + (acc[2][0] + acc[3][0]);
        float d1 = (acc[0][1] + acc[1][1]) + (acc[2][1] + acc[3][1]);
        float d2 = (acc[0][2] + acc[1][2]) + (acc[2][2] + acc[3][2]);
        float d3 = (acc[0][3] + acc[1][3]) + (acc[2][3] + acc[3][3]);
        part[kh][2 * tig][mt * 16 + gid]         = d0;
        part[kh][2 * tig + 1][mt * 16 + gid]     = d1;
        part[kh][2 * tig][mt * 16 + gid + 8]     = d2;
        part[kh][2 * tig + 1][mt * 16 + gid + 8] = d3;

        // -- rinv for this warp's batch row (b = warp), off critical path --
        float mx = lmax[buf][warp][lane & 7];
        mx = fmaxf(mx, __shfl_xor_sync(0xFFFFFFFFu, mx, 1));
        mx = fmaxf(mx, __shfl_xor_sync(0xFFFFFFFFu, mx, 2));
        mx = fmaxf(mx, __shfl_xor_sync(0xFFFFFFFFu, mx, 4));
        const float rv = 1.0f / mx;
        if (lane == 0) c_sh[warp] += (double)logf(mx);
        __syncthreads();

        // -- epilogue: warp = batch row, lane = state pair --
        const int bufn = buf ^ 1;
        const int s0   = lane * 2;
        float2 q0 = *reinterpret_cast<const float2*>(&part[0][warp][s0]);
        float2 q1 = *reinterpret_cast<const float2*>(&part[1][warp][s0]);
        float2 be = *reinterpret_cast<const float2*>(&B_sh[symw][s0]);
        float u0 = (q0.x + q1.x) * rv * be.x;
        float u1 = (q0.y + q1.y) * rv * be.y;
        uint32_t pw = bf16x2(u1, u0);
        uint32_t off = (uint32_t)((bufn * RPC + warp) * RSW + (col0 >> 1) + lane) * 4u;
#pragma unroll
        for (int rr = 0; rr < CPC; rr++)
            st_cluster32(p_rem[rr] + off, pw);

        // per-(CTA, b) slice max, broadcast to all ranks' lmax[bufn]
        float wm = fmaxf(u0, u1);
#pragma unroll
        for (int o = 16; o >= 1; o >>= 1)
            wm = fmaxf(wm, __shfl_xor_sync(0xFFFFFFFFu, wm, o));
        if (lane < CPC) {
            uint32_t lo = (uint32_t)((bufn * RPC + warp) * 8 + r) * 4u;
            st_cluster32(lmax_rem[lane] + lo, __float_as_uint(wm));
        }

        asm volatile("barrier.cluster.arrive.aligned;" ::: "memory");
        asm volatile("barrier.cluster.wait.aligned;"   ::: "memory");
        buf = bufn;
    }

    // ---- alpha_T = log(u_T) + C ----
    {
        const int b  = warp;
        const int s0 = lane * 2;
        uint32_t pw = p_w[buf][b][(col0 >> 1) + lane];
        float u0 = __uint_as_float(pw << 16);
        float u1 = __uint_as_float(pw & 0xFFFF0000u);
        double cc = c_sh[b];
        out[(size_t)(cl * RPC + b) * NS + col0 + s0]     = (float)((double)logf(u0) + cc);
        out[(size_t)(cl * RPC + b) * NS + col0 + s0 + 1] = (float)((double)logf(u1) + cc);
    }
}

// ---------------------------------------------------------------------------
// Kernel 2: loglik[b] = log(sum_s exp(alpha - m) + S*eps) + m, one warp per row
// ---------------------------------------------------------------------------
__global__ void loglik_kernel(float* __restrict__ out) {
    const int b    = blockIdx.x;
    const int lane = threadIdx.x;
    const float* a = out + (size_t)b * NS;
    float v[16];
    float m = -3.0e38f;
#pragma unroll
    for (int i = 0; i < 16; i++) { v[i] = a[lane + i * 32]; m = fmaxf(m, v[i]); }
#pragma unroll
    for (int o = 16; o >= 1; o >>= 1) m = fmaxf(m, __shfl_xor_sync(0xFFFFFFFFu, m, o));
    float s = 0.f;
#pragma unroll
    for (int i = 0; i < 16; i++) s += expf(v[i] - m);
#pragma unroll
    for (int o = 16; o >= 1; o >>= 1) s += __shfl_xor_sync(0xFFFFFFFFu, s, o);
    if (lane == 0) out[NB * NS + b] = logf(s + 512.0f * 1e-16f) + m;
}

// ---------------------------------------------------------------------------
extern "C" void kernel_launch(void* const* d_in, const int* in_sizes, int n_in,
                              void* d_out, int out_size) {
    const float* x  = nullptr;
    const float* A  = nullptr;
    const float* Bm = nullptr;
    for (int i = 0; i < n_in; i++) {
        if      (in_sizes[i] == NB * TB * NM) x  = (const float*)d_in[i];
        else if (in_sizes[i] == NS * NS)      A  = (const float*)d_in[i];
        else if (in_sizes[i] == NM * NS)      Bm = (const float*)d_in[i];
    }
    if (!x  && n_in > 0) x  = (const float*)d_in[0];
    if (!A  && n_in > 1) A  = (const float*)d_in[1];
    if (!Bm && n_in > 2) Bm = (const float*)d_in[2];

    float* out = (float*)d_out;

    extract_sym_kernel<<<(NB * TB * 4) / 256, 256>>>(x);
    hmm_fwd_kernel<<<NCL * CPC, 256>>>(A, Bm, out);
    if (out_size >= NB * NS + NB)
        loglik_kernel<<<NB, 32>>>(out);
}

// round 11
// speedup vs baseline: 3.9072x; 1.2386x over previous
#include <cuda_runtime.h>
#include <math.h>
#include <stdint.h>

// Problem constants
#define TB   8192   // T
#define NB   128    // batch
#define NS   512    // states
#define NM   64     // symbols
#define NCL  16     // clusters (batch groups)
#define RPC  8      // batch rows per cluster
#define CPC  8      // CTAs per cluster (state slices)
#define NC   64     // state columns per CTA
#define RSW  260    // p row stride in 32-bit words (256 data + 4 pad)
#define PSD  76     // part s-dim pad (conflict-free ST + LD)
#define TXB  8448   // expected tx bytes/step: 8 src * (1024 p + 32 lmax)

// Static device scratch
__device__ unsigned short g_sym[NB * TB];            // 2 MB: symbol per (b,t)

// ---- helpers ---------------------------------------------------------------
__device__ __forceinline__ uint32_t bf16x2(float hi, float lo) {
    uint32_t d;
    asm("cvt.rn.bf16x2.f32 %0, %1, %2;" : "=r"(d) : "f"(hi), "f"(lo));
    return d;
}
__device__ __forceinline__ void mma16816(float* d, const uint32_t* a,
                                         uint32_t b0, uint32_t b1) {
    asm("mma.sync.aligned.m16n8k16.row.col.f32.bf16.bf16.f32 "
        "{%0,%1,%2,%3}, {%4,%5,%6,%7}, {%8,%9}, {%0,%1,%2,%3};"
        : "+f"(d[0]), "+f"(d[1]), "+f"(d[2]), "+f"(d[3])
        : "r"(a[0]), "r"(a[1]), "r"(a[2]), "r"(a[3]), "r"(b0), "r"(b1));
}
__device__ __forceinline__ uint32_t mapa_sh(uint32_t addr, uint32_t rank) {
    uint32_t d;
    asm("mapa.shared::cluster.u32 %0, %1, %2;" : "=r"(d) : "r"(addr), "r"(rank));
    return d;
}
__device__ __forceinline__ uint32_t smem_u32(const void* p) {
    uint32_t a;
    asm("{ .reg .u64 t; cvta.to.shared.u64 t, %1; cvt.u32.u64 %0, t; }"
        : "=r"(a) : "l"(p));
    return a;
}
// st.async: data word + tx-completion to the remote CTA's mbarrier
__device__ __forceinline__ void st_async64(uint32_t raddr, unsigned long long v,
                                           uint32_t rmbar) {
    asm volatile("st.async.shared::cluster.mbarrier::complete_tx::bytes.u64 "
                 "[%0], %1, [%2];" :: "r"(raddr), "l"(v), "r"(rmbar) : "memory");
}
__device__ __forceinline__ void st_async32(uint32_t raddr, uint32_t v,
                                           uint32_t rmbar) {
    asm volatile("st.async.shared::cluster.mbarrier::complete_tx::bytes.u32 "
                 "[%0], %1, [%2];" :: "r"(raddr), "r"(v), "r"(rmbar) : "memory");
}
__device__ __forceinline__ void mbar_init(uint32_t addr, uint32_t count) {
    asm volatile("mbarrier.init.shared.b64 [%0], %1;" :: "r"(addr), "r"(count)
                 : "memory");
}
__device__ __forceinline__ void mbar_arm(uint32_t addr, uint32_t tx) {
    asm volatile("mbarrier.arrive.expect_tx.shared.b64 _, [%0], %1;"
                 :: "r"(addr), "r"(tx) : "memory");
}
__device__ __forceinline__ void mbar_wait(uint32_t addr, int parity) {
    asm volatile(
        "{\n\t.reg .pred P;\n"
        "W%=:\n\t"
        "mbarrier.try_wait.parity.acquire.cluster.shared::cta.b64 P, [%0], %1, 0x989680;\n\t"
        "@P bra D%=;\n\t"
        "bra W%=;\n"
        "D%=:\n\t}"
        :: "r"(addr), "r"(parity) : "memory");
}

// ---------------------------------------------------------------------------
// Kernel 0: collapse one-hot x[b,t,:] -> symbol index. 4 threads per position.
// ---------------------------------------------------------------------------
__global__ void extract_sym_kernel(const float* __restrict__ x) {
    int g = blockIdx.x * blockDim.x + threadIdx.x;
    int pos  = g >> 2;
    int part = g & 3;
    const float4* xp = reinterpret_cast<const float4*>(x) + (size_t)pos * 16 + part * 4;
    int found = 0;
#pragma unroll
    for (int i = 0; i < 4; i++) {
        float4 v = xp[i];
        int base = part * 16 + i * 4;
        if (v.x > 0.5f) found = base;
        if (v.y > 0.5f) found = base + 1;
        if (v.z > 0.5f) found = base + 2;
        if (v.w > 0.5f) found = base + 3;
    }
    found = max(found, __shfl_xor_sync(0xFFFFFFFFu, found, 1));
    found = max(found, __shfl_xor_sync(0xFFFFFFFFu, found, 2));
    if (part == 0) g_sym[pos] = (unsigned short)found;
}

// ---------------------------------------------------------------------------
// Kernel 1: persistent clustered forward recurrence, bf16 HMMA + fp32 accum,
//   st.async data-driven sync (NO per-step cluster barrier).
//   grid = 128 CTAs, cluster (8,1,1), 256 threads.
//   MMA phase:  warp w -> (mt = w&3 m16-tile, kh = w>>2 K-half), 16 HMMA.
//   Epilogue:   warp w -> batch row b=w, lane -> state pair; st.async.u64 push.
// ---------------------------------------------------------------------------
__global__ void __cluster_dims__(CPC, 1, 1) __launch_bounds__(256, 1)
hmm_fwd_kernel(const float* __restrict__ A, const float* __restrict__ Bm,
               float* __restrict__ out)
{
    __shared__ uint32_t p_w[2][RPC][RSW];          // bf16-pair p, double buffered
    __shared__ float    part[2][2][RPC][PSD];      // [buf][kh][n][m] partials
    __shared__ float    B_sh[NM][NC];              // emission slice
    __shared__ float    lmax[2][RPC][8];           // per-CTA slice maxes
    __shared__ double   c_sh[RPC];                 // running log-scale per row
    __shared__ __align__(8) unsigned long long mbar_sh[2];

    const int tid  = threadIdx.x;
    const int lane = tid & 31;
    const int warp = tid >> 5;
    const int gid  = lane >> 2;   // mma group id
    const int tig  = lane & 3;    // thread in group
    const int mt   = warp & 3;    // m16 tile
    const int kh   = warp >> 2;   // K-half

    uint32_t r_;
    asm("mov.u32 %0, %%cluster_ctarank;" : "=r"(r_));
    const int r    = (int)r_;
    const int cl   = (int)blockIdx.x / CPC;
    const int col0 = r * NC;

    const uint32_t p_base    = smem_u32(&p_w[0][0][0]);
    const uint32_t lmax_base = smem_u32(&lmax[0][0][0]);
    const uint32_t mbar_loc  = smem_u32(&mbar_sh[0]);
    uint32_t p_rem[CPC], lmax_rem[CPC], mbar_rem[CPC];
#pragma unroll
    for (int rr = 0; rr < CPC; rr++) {
        p_rem[rr]    = mapa_sh(p_base, rr);
        lmax_rem[rr] = mapa_sh(lmax_base, rr);
        mbar_rem[rr] = mapa_sh(mbar_loc, rr);
    }

    if (tid == 0) { mbar_init(mbar_loc, 1); mbar_init(mbar_loc + 8, 1); }

    // ---- A fragments (constant): areg[16 kc][4], this warp's (mt, kh) ----
    uint32_t areg[16][4];
#pragma unroll
    for (int kc = 0; kc < 16; kc++) {
        int m0 = col0 + mt * 16 + gid;
        int k0 = kh * 256 + kc * 16 + tig * 2;
        const float* A0 = A + (size_t)k0 * NS;
        areg[kc][0] = bf16x2(A0[NS + m0],          A0[m0]);
        areg[kc][1] = bf16x2(A0[NS + m0 + 8],      A0[m0 + 8]);
        areg[kc][2] = bf16x2(A0[9 * NS + m0],      A0[8 * NS + m0]);
        areg[kc][3] = bf16x2(A0[9 * NS + m0 + 8],  A0[8 * NS + m0 + 8]);
    }

    // ---- emission slice (fp32) ----
    for (int i = tid; i < NM * NC; i += 256)
        B_sh[i >> 6][i & 63] = Bm[(size_t)(i >> 6) * NS + col0 + (i & 63)];

    if (tid < RPC) c_sh[tid] = 0.0;

    // ---- init buffer 0: p[b][k] = (k==0) ? B[sym0][0] : 0 (bf16 pairs) ----
    for (int i = tid; i < RPC * RSW; i += 256) {
        int b = i / RSW, w = i % RSW;
        uint32_t v = 0;
        if (w == 0) {
            int s0 = g_sym[(size_t)(cl * RPC + b) * TB];
            v = bf16x2(0.0f, Bm[(size_t)s0 * NS]);
        }
        p_w[0][b][w] = v;
    }
    if (tid < RPC * 8) {
        int b = tid >> 3;
        int s0 = g_sym[(size_t)(cl * RPC + b) * TB];
        lmax[0][b][tid & 7] = Bm[(size_t)s0 * NS];
    }
    __syncthreads();
    asm volatile("barrier.cluster.arrive.aligned;" ::: "memory");
    asm volatile("barrier.cluster.wait.aligned;"   ::: "memory");

    int buf = 0, ph0 = 0, ph1 = 0;
    for (int t = 1; t < TB; t++) {
        const int bufn = buf ^ 1;
        // symbol for this warp's epilogue row (independent; overlaps wait)
        const unsigned short symw = __ldg(&g_sym[(size_t)(cl * RPC + warp) * TB + t]);

        // arm receiver mbarrier for this step's incoming data (buffer bufn)
        if (tid == 0) mbar_arm(mbar_loc + (bufn << 3), TXB);

        // wait for all of last step's data (buffer buf) to have landed
        if (t > 1) {
            if (buf == 0) { mbar_wait(mbar_loc,     ph0); ph0 ^= 1; }
            else          { mbar_wait(mbar_loc + 8, ph1); ph1 ^= 1; }
        }

        // -- B fragments for (b = gid, K-half kh) --
        const uint32_t* pb = &p_w[buf][0][0];
        uint32_t bf0[16], bf1[16];
#pragma unroll
        for (int kc = 0; kc < 16; kc++) {
            int w0 = gid * RSW + kh * 128 + kc * 8 + tig;
            bf0[kc] = pb[w0];
            bf1[kc] = pb[w0 + 4];
        }

        // -- 16 HMMA over 8 interleaved accumulator chains --
        float acc[8][4];
#pragma unroll
        for (int j = 0; j < 8; j++) { acc[j][0] = acc[j][1] = acc[j][2] = acc[j][3] = 0.f; }
#pragma unroll
        for (int kc = 0; kc < 16; kc++)
            mma16816(acc[kc & 7], areg[kc], bf0[kc], bf1[kc]);
#pragma unroll
        for (int cjs = 0; cjs < 4; cjs++) {
            float d = ((acc[0][cjs] + acc[1][cjs]) + (acc[2][cjs] + acc[3][cjs]))
                    + ((acc[4][cjs] + acc[5][cjs]) + (acc[6][cjs] + acc[7][cjs]));
            int row = 2 * tig + (cjs & 1);
            int m   = mt * 16 + gid + (cjs >> 1) * 8;
            part[buf][kh][row][m] = d;
        }

        // -- rinv for this warp's batch row (b = warp), off critical path --
        float mx = lmax[buf][warp][lane & 7];
        mx = fmaxf(mx, __shfl_xor_sync(0xFFFFFFFFu, mx, 1));
        mx = fmaxf(mx, __shfl_xor_sync(0xFFFFFFFFu, mx, 2));
        mx = fmaxf(mx, __shfl_xor_sync(0xFFFFFFFFu, mx, 4));
        const float rv = 1.0f / mx;
        if (lane == 0) c_sh[warp] += (double)logf(mx);
        __syncthreads();

        // -- epilogue: warp = batch row, lane = state pair; st.async push --
        const int s0 = lane * 2;
        float2 q0 = *reinterpret_cast<const float2*>(&part[buf][0][warp][s0]);
        float2 q1 = *reinterpret_cast<const float2*>(&part[buf][1][warp][s0]);
        float2 be = *reinterpret_cast<const float2*>(&B_sh[symw][s0]);
        float u0 = (q0.x + q1.x) * rv * be.x;
        float u1 = (q0.y + q1.y) * rv * be.y;
        uint32_t pw = bf16x2(u1, u0);
        uint32_t pw_hi = __shfl_xor_sync(0xFFFFFFFFu, pw, 1);
        const uint32_t rmb_off = (uint32_t)(bufn << 3);
        if (!(lane & 1)) {
            unsigned long long v2 = ((unsigned long long)pw_hi << 32) | pw;
            uint32_t off = (uint32_t)((bufn * RPC + warp) * RSW + (col0 >> 1) + lane) * 4u;
#pragma unroll
            for (int rr = 0; rr < CPC; rr++)
                st_async64(p_rem[rr] + off, v2, mbar_rem[rr] + rmb_off);
        }
        // per-(CTA, b) slice max -> all ranks' lmax[bufn][warp][r]
        float wm = fmaxf(u0, u1);
#pragma unroll
        for (int o = 16; o >= 1; o >>= 1)
            wm = fmaxf(wm, __shfl_xor_sync(0xFFFFFFFFu, wm, o));
        if ((lane & 1) && lane < 16) {
            int rr = lane >> 1;
            uint32_t lo = (uint32_t)((bufn * RPC + warp) * 8 + r) * 4u;
            st_async32(lmax_rem[rr] + lo, __float_as_uint(wm), mbar_rem[rr] + rmb_off);
        }
        buf = bufn;
    }

    // final wait: last step's data
    if (buf == 0) { mbar_wait(mbar_loc,     ph0); }
    else          { mbar_wait(mbar_loc + 8, ph1); }

    // ---- alpha_T = log(u_T) + C ----
    {
        const int b  = warp;
        const int s0 = lane * 2;
        uint32_t pw = p_w[buf][b][(col0 >> 1) + lane];
        float u0 = __uint_as_float(pw << 16);
        float u1 = __uint_as_float(pw & 0xFFFF0000u);
        double cc = c_sh[b];
        out[(size_t)(cl * RPC + b) * NS + col0 + s0]     = (float)((double)logf(u0) + cc);
        out[(size_t)(cl * RPC + b) * NS + col0 + s0 + 1] = (float)((double)logf(u1) + cc);
    }
    asm volatile("barrier.cluster.arrive.aligned;" ::: "memory");
    asm volatile("barrier.cluster.wait.aligned;"   ::: "memory");
}

// ---------------------------------------------------------------------------
// Kernel 2: loglik[b] = log(sum_s exp(alpha - m) + S*eps) + m, one warp per row
// ---------------------------------------------------------------------------
__global__ void loglik_kernel(float* __restrict__ out) {
    const int b    = blockIdx.x;
    const int lane = threadIdx.x;
    const float* a = out + (size_t)b * NS;
    float v[16];
    float m = -3.0e38f;
#pragma unroll
    for (int i = 0; i < 16; i++) { v[i] = a[lane + i * 32]; m = fmaxf(m, v[i]); }
#pragma unroll
    for (int o = 16; o >= 1; o >>= 1) m = fmaxf(m, __shfl_xor_sync(0xFFFFFFFFu, m, o));
    float s = 0.f;
#pragma unroll
    for (int i = 0; i < 16; i++) s += expf(v[i] - m);
#pragma unroll
    for (int o = 16; o >= 1; o >>= 1) s += __shfl_xor_sync(0xFFFFFFFFu, s, o);
    if (lane == 0) out[NB * NS + b] = logf(s + 512.0f * 1e-16f) + m;
}

// ---------------------------------------------------------------------------
extern "C" void kernel_launch(void* const* d_in, const int* in_sizes, int n_in,
                              void* d_out, int out_size) {
    const float* x  = nullptr;
    const float* A  = nullptr;
    const float* Bm = nullptr;
    for (int i = 0; i < n_in; i++) {
        if      (in_sizes[i] == NB * TB * NM) x  = (const float*)d_in[i];
        else if (in_sizes[i] == NS * NS)      A  = (const float*)d_in[i];
        else if (in_sizes[i] == NM * NS)      Bm = (const float*)d_in[i];
    }
    if (!x  && n_in > 0) x  = (const float*)d_in[0];
    if (!A  && n_in > 1) A  = (const float*)d_in[1];
    if (!Bm && n_in > 2) Bm = (const float*)d_in[2];

    float* out = (float*)d_out;

    extract_sym_kernel<<<(NB * TB * 4) / 256, 256>>>(x);
    hmm_fwd_kernel<<<NCL * CPC, 256>>>(A, Bm, out);
    if (out_size >= NB * NS + NB)
        loglik_kernel<<<NB, 32>>>(out);
}